// round 5
// baseline (speedup 1.0000x reference)
#include <cuda_runtime.h>
#include <cuda_fp16.h>
#include <math.h>
#include <stdint.h>

// ---------------- problem constants ----------------
#define Bc 2
#define Sc 2048
#define Dc 1024
#define Hc 16
#define DHc 64
#define Fc 4096
#define Ec 8
#define NTOK (Bc * Sc)
#define LN_EPS 1e-6f

// ---------------- fp32 scratch ----------------
static const size_t F_SC    = 0;                                   // scores  B*H*S*S
static const size_t F_ATTN  = F_SC  + (size_t)Bc * Hc * Sc * Sc;
static const size_t F_INT   = F_ATTN + (size_t)NTOK * Dc;
static const size_t F_MOE   = F_INT  + (size_t)NTOK * Dc;
static const size_t F_GATE  = F_MOE  + (size_t)NTOK * Dc;
static const size_t F_TOTAL = F_GATE + (size_t)NTOK * Ec;
__device__ float g_f32[F_TOTAL];

// ---------------- fp16 scratch ----------------
static const size_t H_HID  = 0;
static const size_t H_Q    = H_HID + (size_t)NTOK * Dc;
static const size_t H_K    = H_Q   + (size_t)NTOK * Dc;
static const size_t H_VT   = H_K   + (size_t)NTOK * Dc;     // [B,H,DH,S]
static const size_t H_CTX  = H_VT  + (size_t)NTOK * Dc;
static const size_t H_INT  = H_CTX + (size_t)NTOK * Dc;
static const size_t H_HB   = H_INT + (size_t)NTOK * Dc;     // 4096*4096
static const size_t H_PR   = H_HB  + (size_t)NTOK * Fc;     // probs B*H*S*S
static const size_t H_WQ   = H_PR  + (size_t)Bc * Hc * Sc * Sc;
static const size_t H_WK   = H_WQ  + (size_t)Dc * Dc;
static const size_t H_WV   = H_WK  + (size_t)Dc * Dc;
static const size_t H_WO   = H_WV  + (size_t)Dc * Dc;
static const size_t H_W1   = H_WO  + (size_t)Dc * Dc;       // [E][N=F,K=D]
static const size_t H_W2   = H_W1  + (size_t)Ec * Dc * Fc;  // [E][N=D,K=F]
static const size_t H_TOTAL= H_W2  + (size_t)Ec * Fc * Dc;
__device__ __half g_f16[H_TOTAL];

// ---------------- PTX helpers (sm_100-safe: mma.sync / ldmatrix / cp.async) --
__device__ __forceinline__ uint32_t smem_u32(const void* p) {
    uint32_t a;
    asm("{ .reg .u64 t; cvta.to.shared.u64 t, %1; cvt.u32.u64 %0, t; }" : "=r"(a) : "l"(p));
    return a;
}
__device__ __forceinline__ void cp16(uint32_t s, const void* g) {
    asm volatile("cp.async.cg.shared.global [%0], [%1], 16;" :: "r"(s), "l"(g));
}
#define CP_COMMIT() asm volatile("cp.async.commit_group;" ::: "memory")
#define CP_WAIT(n)  asm volatile("cp.async.wait_group %0;" :: "n"(n) : "memory")

__device__ __forceinline__ void ldm_x4(uint32_t* r, uint32_t addr) {
    asm volatile("ldmatrix.sync.aligned.m8n8.x4.shared.b16 {%0,%1,%2,%3}, [%4];"
        : "=r"(r[0]), "=r"(r[1]), "=r"(r[2]), "=r"(r[3]) : "r"(addr));
}
__device__ __forceinline__ void mma16816(float* c, const uint32_t* a, const uint32_t* b) {
    asm volatile(
        "mma.sync.aligned.m16n8k16.row.col.f32.f16.f16.f32 "
        "{%0,%1,%2,%3}, {%4,%5,%6,%7}, {%8,%9}, {%0,%1,%2,%3};"
        : "+f"(c[0]), "+f"(c[1]), "+f"(c[2]), "+f"(c[3])
        : "r"(a[0]), "r"(a[1]), "r"(a[2]), "r"(a[3]), "r"(b[0]), "r"(b[1]));
}

__device__ __forceinline__ float gelu_tanh(float x) {
    float x3 = x * x * x;
    float t  = tanhf(0.7978845608028654f * (x + 0.044715f * x3));
    return 0.5f * x * (1.0f + t);
}
__device__ __forceinline__ uint32_t pack_h2(float a, float b) {
    __half2 h = __floats2half2_rn(a, b);
    return *reinterpret_cast<uint32_t*>(&h);
}

// ============================================================================
// HMMA GEMM: C[M-tiles of MT, N-tiles of NT] = A[M,K] * B[N,K]^T
// 256 threads = 8 warps (4 along M x 2 along N); warp tile (MT/4) x (NT/2).
// BK=32, mma.m16n8k16, 3-stage cp.async pipeline, ONE __syncthreads / chunk.
// EPI: 0 = fp32 C = acc + bias?          3 = fp32 C = acc*alpha + mask
//      1 = fp16 C16 = gelu(acc + bias)   6 = fp16 C16 = acc + bias?
//      2 = fp32 C = gate*(acc+bias)      5 = fp32 C += gate*(acc+bias)
//      7 = fp16 V^T scatter: acc + bias -> C16[b,h,d,s]
// ============================================================================
#define SPAD 40          // smem row stride in halves (80 bytes)
#define STAGES 3

template <int MT, int NT, int EPI>
__global__ __launch_bounds__(256)
void hgemm(const __half* __restrict__ A, const __half* __restrict__ B,
           float* __restrict__ C, __half* __restrict__ C16,
           const float* __restrict__ bias, const float* __restrict__ aux,
           int K, int lda, int ldb, int ldc, int ldaux, float alpha, int Hdim,
           long long aOB, long long aOH, long long bOB, long long bOH,
           long long cOB, long long cOH, long long xOB)
{
    extern __shared__ __half smem[];

    constexpr int WM = MT / 4;       // warp M extent
    constexpr int WN = NT / 2;       // warp N extent
    constexpr int MI = WM / 16;      // m-fragments per warp (16-row frags)
    constexpr int NF = WN / 8;       // n-fragments per warp (8-col frags)

    const int tid = threadIdx.x, wid = tid >> 5, lane = tid & 31;
    const int wm = wid & 3, wn = wid >> 2;          // warp grid 4 x 2

    const int m0 = blockIdx.y * MT, n0 = blockIdx.x * NT;
    const int z = blockIdx.z, bb = z / Hdim, hh = z - bb * Hdim;
    A += (size_t)bb * aOB + (size_t)hh * aOH;
    B += (size_t)bb * bOB + (size_t)hh * bOH;
    const long long coff = (long long)bb * cOB + (long long)hh * cOH;

    const uint32_t ABUF = (uint32_t)MT * SPAD * 2;        // bytes per A stage
    const uint32_t BBUF = (uint32_t)NT * SPAD * 2;        // bytes per B stage
    const uint32_t abase = smem_u32(smem);
    const uint32_t bbase = abase + STAGES * ABUF;

    float acc[MI][NF][4];
#pragma unroll
    for (int i = 0; i < MI; i++)
#pragma unroll
        for (int j = 0; j < NF; j++)
#pragma unroll
            for (int r = 0; r < 4; r++) acc[i][j][r] = 0.0f;

    const int nc = K >> 5;  // BK = 32

    // ---- tile loader (tile c into stage buf) via cp.async
    auto load_tile = [&](int c, int buf) {
        const __half* Ab = A + (size_t)m0 * lda + (size_t)c * 32;
#pragma unroll
        for (int it = 0; it < MT / 64; it++) {
            int lin = it * 256 + tid;
            int row = lin >> 2, seg = lin & 3;
            cp16(abase + buf * ABUF + row * (SPAD * 2) + seg * 16,
                 Ab + (size_t)row * lda + seg * 8);
        }
        const __half* Bb = B + (size_t)n0 * ldb + (size_t)c * 32;
#pragma unroll
        for (int it = 0; it < NT / 64; it++) {
            int lin = it * 256 + tid;
            int row = lin >> 2, seg = lin & 3;
            cp16(bbase + buf * BBUF + row * (SPAD * 2) + seg * 16,
                 Bb + (size_t)row * ldb + seg * 8);
        }
    };

    // ---- prologue: fill STAGES-1 stages
#pragma unroll
    for (int s = 0; s < STAGES - 1; s++) {
        if (s < nc) load_tile(s, s);
        CP_COMMIT();
    }

    for (int c = 0; c < nc; c++) {
        CP_WAIT(STAGES - 2);               // tile c resident
        __syncthreads();                   // all warps done with stage (c-1)%STAGES
        const int nxt = c + STAGES - 1;
        if (nxt < nc) load_tile(nxt, nxt % STAGES);
        CP_COMMIT();                       // always commit (tail = empty groups)

        const int buf = c % STAGES;
        const uint32_t ab = abase + buf * ABUF;
        const uint32_t bbf = bbase + buf * BBUF;

#pragma unroll
        for (int ks = 0; ks < 2; ks++) {
            // A fragments: MI x (16x16)
            uint32_t af[MI][4];
#pragma unroll
            for (int mi = 0; mi < MI; mi++) {
                int row = wm * WM + mi * 16 + (lane & 15);
                int col = ks * 16 + (lane >> 4) * 8;
                ldm_x4(af[mi], ab + row * (SPAD * 2) + col * 2);
            }
            // B fragments: NF x (k16 x n8), loaded in pairs
            uint32_t bf[NF][2];
#pragma unroll
            for (int p = 0; p < NF / 2; p++) {
                int row = wn * WN + p * 16 + (lane & 7) + ((lane >> 4) << 3);
                int col = ks * 16 + ((lane >> 3) & 1) * 8;
                uint32_t t[4];
                ldm_x4(t, bbf + row * (SPAD * 2) + col * 2);
                bf[2 * p][0] = t[0]; bf[2 * p][1] = t[1];
                bf[2 * p + 1][0] = t[2]; bf[2 * p + 1][1] = t[3];
            }
#pragma unroll
            for (int mi = 0; mi < MI; mi++)
#pragma unroll
                for (int nj = 0; nj < NF; nj++)
                    mma16816(acc[mi][nj], af[mi], bf[nj]);
        }
    }

    // -------- epilogue --------
#pragma unroll
    for (int mi = 0; mi < MI; mi++) {
#pragma unroll
        for (int nj = 0; nj < NF; nj++) {
            const int r0 = m0 + wm * WM + mi * 16 + (lane >> 2);
            const int cc = n0 + wn * WN + nj * 8 + (lane & 3) * 2;
#pragma unroll
            for (int h = 0; h < 2; h++) {
                const int row = r0 + h * 8;
                const float v0 = acc[mi][nj][2 * h + 0];
                const float v1 = acc[mi][nj][2 * h + 1];
                if (EPI == 0) {
                    float b0 = bias ? bias[cc] : 0.f, b1 = bias ? bias[cc + 1] : 0.f;
                    float2 o = make_float2(v0 + b0, v1 + b1);
                    *(float2*)(C + coff + (size_t)row * ldc + cc) = o;
                } else if (EPI == 3) {
                    const float* mp = aux + (size_t)bb * xOB + (size_t)row * ldaux + cc;
                    float2 o = make_float2(v0 * alpha + mp[0], v1 * alpha + mp[1]);
                    *(float2*)(C + coff + (size_t)row * ldc + cc) = o;
                } else if (EPI == 2 || EPI == 5) {
                    const float gt = aux[(size_t)row * ldaux];
                    float* cp = C + coff + (size_t)row * ldc + cc;
                    float2 o = (EPI == 5) ? *(float2*)cp : make_float2(0.f, 0.f);
                    o.x += gt * (v0 + bias[cc]);
                    o.y += gt * (v1 + bias[cc + 1]);
                    *(float2*)cp = o;
                } else if (EPI == 1 || EPI == 6) {
                    float o0 = v0 + (bias ? bias[cc] : 0.f);
                    float o1 = v1 + (bias ? bias[cc + 1] : 0.f);
                    if (EPI == 1) { o0 = gelu_tanh(o0); o1 = gelu_tanh(o1); }
                    *(uint32_t*)(C16 + coff + (size_t)row * ldc + cc) = pack_h2(o0, o1);
                } else if (EPI == 7) {
                    const int b_ = row >> 11, s_ = row & 2047;
                    float o0 = v0 + (bias ? bias[cc] : 0.f);
                    float o1 = v1 + (bias ? bias[cc + 1] : 0.f);
                    const int h0 = cc >> 6, d0 = cc & 63;
                    const int h1 = (cc + 1) >> 6, d1 = (cc + 1) & 63;
                    C16[((size_t)((b_ * Hc + h0) * DHc + d0)) * Sc + s_] = __float2half(o0);
                    C16[((size_t)((b_ * Hc + h1) * DHc + d1)) * Sc + s_] = __float2half(o1);
                }
            }
        }
    }
}

static const int SMEM_256_128 = STAGES * (256 + 128) * SPAD * 2;  // 92160
static const int SMEM_128_64  = STAGES * (128 + 64) * SPAD * 2;   // 46080

// ---------------- fp32 -> fp16 convert ----------------
__global__ void conv16(const float* __restrict__ s, __half* __restrict__ d, int n4)
{
    int i = blockIdx.x * blockDim.x + threadIdx.x;
    if (i < n4) {
        float4 v = ((const float4*)s)[i];
        uint2 u;
        u.x = pack_h2(v.x, v.y); u.y = pack_h2(v.z, v.w);
        ((uint2*)d)[i] = u;
    }
}

// ---------------- transpose-convert: src [K,N] f32 -> dst [N,K] f16 --------
__global__ void tconv(const float* __restrict__ src, __half* __restrict__ dst, int K, int N)
{
    __shared__ float t[32][33];
    src += (size_t)blockIdx.z * K * N;
    dst += (size_t)blockIdx.z * K * N;
    const int k0 = blockIdx.y * 32, n0 = blockIdx.x * 32;
    const int x = threadIdx.x, y = threadIdx.y;
#pragma unroll
    for (int i = 0; i < 32; i += 8)
        t[y + i][x] = src[(size_t)(k0 + y + i) * N + n0 + x];
    __syncthreads();
#pragma unroll
    for (int i = 0; i < 32; i += 8)
        dst[(size_t)(n0 + y + i) * K + k0 + x] = __float2half(t[x][y + i]);
}

// ---------------- softmax over rows of length 2048, fp32 in -> fp16 out ----
__global__ void softmax2048(const float* __restrict__ sc, __half* __restrict__ pr)
{
    __shared__ float red[256];
    const size_t base = (size_t)blockIdx.x * 2048;
    const int tid = threadIdx.x;
    float v[8];
    float mx = -INFINITY;
#pragma unroll
    for (int i = 0; i < 8; i++) { v[i] = sc[base + tid + i * 256]; mx = fmaxf(mx, v[i]); }
    red[tid] = mx; __syncthreads();
    for (int s = 128; s > 0; s >>= 1) { if (tid < s) red[tid] = fmaxf(red[tid], red[tid + s]); __syncthreads(); }
    mx = red[0]; __syncthreads();
    float sum = 0.f;
#pragma unroll
    for (int i = 0; i < 8; i++) { v[i] = expf(v[i] - mx); sum += v[i]; }
    red[tid] = sum; __syncthreads();
    for (int s = 128; s > 0; s >>= 1) { if (tid < s) red[tid] += red[tid + s]; __syncthreads(); }
    const float inv = 1.0f / red[0];
#pragma unroll
    for (int i = 0; i < 8; i++) pr[base + tid + i * 256] = __float2half(v[i] * inv);
}

// ---------------- LayerNorm(x + r), fp32 out + optional fp16 copy ----------
__global__ void ln_residual(const float* __restrict__ x, const float* __restrict__ r,
                            const float* __restrict__ g, const float* __restrict__ b,
                            float* __restrict__ out, __half* __restrict__ out16)
{
    __shared__ float red[256];
    const size_t base = (size_t)blockIdx.x * Dc;
    const int tid = threadIdx.x;
    float v[4]; float s = 0.f;
#pragma unroll
    for (int i = 0; i < 4; i++) { const int c = tid + i * 256; v[i] = x[base + c] + r[base + c]; s += v[i]; }
    red[tid] = s; __syncthreads();
    for (int st = 128; st > 0; st >>= 1) { if (tid < st) red[tid] += red[tid + st]; __syncthreads(); }
    const float mean = red[0] * (1.0f / Dc); __syncthreads();
    float ss = 0.f;
#pragma unroll
    for (int i = 0; i < 4; i++) { const float d = v[i] - mean; ss += d * d; }
    red[tid] = ss; __syncthreads();
    for (int st = 128; st > 0; st >>= 1) { if (tid < st) red[tid] += red[tid + st]; __syncthreads(); }
    const float rstd = rsqrtf(red[0] * (1.0f / Dc) + LN_EPS);
#pragma unroll
    for (int i = 0; i < 4; i++) {
        const int c = tid + i * 256;
        const float o = (v[i] - mean) * rstd * g[c] + b[c];
        out[base + c] = o;
        if (out16) out16[base + c] = __float2half(o);
    }
}

// ---------------- gate: softmax(x @ gate_w + gate_b) over E=8 --------------
__global__ void gate_kernel(const float* __restrict__ x, const float* __restrict__ gw,
                            const float* __restrict__ gb,
                            float* __restrict__ gate, float* __restrict__ gate_out)
{
    const int m = blockIdx.x;
    const int tid = threadIdx.x;
    const int wid = tid >> 5, lane = tid & 31;
    __shared__ float logits[Ec];
    float s = 0.f;
    const float* xr = x + (size_t)m * Dc;
    for (int d = lane; d < Dc; d += 32) s += xr[d] * gw[d * Ec + wid];
#pragma unroll
    for (int o = 16; o > 0; o >>= 1) s += __shfl_down_sync(0xffffffffu, s, o);
    if (lane == 0) logits[wid] = s + gb[wid];
    __syncthreads();
    if (tid == 0) {
        float mx = logits[0];
#pragma unroll
        for (int e = 1; e < Ec; e++) mx = fmaxf(mx, logits[e]);
        float p[Ec]; float sum = 0.f;
#pragma unroll
        for (int e = 0; e < Ec; e++) { p[e] = expf(logits[e] - mx); sum += p[e]; }
        const float inv = 1.0f / sum;
#pragma unroll
        for (int e = 0; e < Ec; e++) {
            const float pv = p[e] * inv;
            gate[(size_t)m * Ec + e] = pv;
            if (gate_out) gate_out[(size_t)m * Ec + e] = pv;
        }
    }
}

// ---------------- launch ----------------------------------------------------
extern "C" void kernel_launch(void* const* d_in, const int* in_sizes, int n_in,
                              void* d_out, int out_size)
{
    const float* hidden = (const float*)d_in[0];
    const float* mask   = (const float*)d_in[1];
    const float* wq = (const float*)d_in[2];  const float* bq = (const float*)d_in[3];
    const float* wk = (const float*)d_in[4];  const float* bk = (const float*)d_in[5];
    const float* wv = (const float*)d_in[6];  const float* bv = (const float*)d_in[7];
    const float* wo = (const float*)d_in[8];  const float* bo = (const float*)d_in[9];
    const float* ln1_g = (const float*)d_in[10]; const float* ln1_b = (const float*)d_in[11];
    const float* gate_w = (const float*)d_in[12]; const float* gate_b = (const float*)d_in[13];
    const float* w1 = (const float*)d_in[14]; const float* b1 = (const float*)d_in[15];
    const float* w2 = (const float*)d_in[16]; const float* b2 = (const float*)d_in[17];
    const float* ln2_g = (const float*)d_in[18]; const float* ln2_b = (const float*)d_in[19];

    float* f32 = nullptr;  __half* f16 = nullptr;
    cudaGetSymbolAddress((void**)&f32, g_f32);
    cudaGetSymbolAddress((void**)&f16, g_f16);

    float*  scores = f32 + F_SC;
    float*  attn   = f32 + F_ATTN;
    float*  inter  = f32 + F_INT;
    float*  moe    = f32 + F_MOE;
    float*  gate   = f32 + F_GATE;
    __half* hid16  = f16 + H_HID;
    __half* q16    = f16 + H_Q;
    __half* k16    = f16 + H_K;
    __half* vT16   = f16 + H_VT;
    __half* ctx16  = f16 + H_CTX;
    __half* int16_ = f16 + H_INT;
    __half* h16    = f16 + H_HB;
    __half* pr16   = f16 + H_PR;
    __half* wqT = f16 + H_WQ; __half* wkT = f16 + H_WK;
    __half* wvT = f16 + H_WV; __half* woT = f16 + H_WO;
    __half* w1T = f16 + H_W1; __half* w2T = f16 + H_W2;

    float* out = (float*)d_out;
    float* gate_out = nullptr;
    if ((size_t)out_size >= (size_t)NTOK * Dc + (size_t)NTOK * Ec)
        gate_out = out + (size_t)NTOK * Dc;

    // raise dynamic smem limits (host-side attribute sets; not stream ops)
    cudaFuncSetAttribute(hgemm<256,128,0>, cudaFuncAttributeMaxDynamicSharedMemorySize, SMEM_256_128);
    cudaFuncSetAttribute(hgemm<256,128,1>, cudaFuncAttributeMaxDynamicSharedMemorySize, SMEM_256_128);
    cudaFuncSetAttribute(hgemm<256,128,2>, cudaFuncAttributeMaxDynamicSharedMemorySize, SMEM_256_128);
    cudaFuncSetAttribute(hgemm<256,128,3>, cudaFuncAttributeMaxDynamicSharedMemorySize, SMEM_256_128);
    cudaFuncSetAttribute(hgemm<256,128,5>, cudaFuncAttributeMaxDynamicSharedMemorySize, SMEM_256_128);
    cudaFuncSetAttribute(hgemm<256,128,6>, cudaFuncAttributeMaxDynamicSharedMemorySize, SMEM_256_128);
    cudaFuncSetAttribute(hgemm<256,128,7>, cudaFuncAttributeMaxDynamicSharedMemorySize, SMEM_256_128);
    cudaFuncSetAttribute(hgemm<128,64,6>,  cudaFuncAttributeMaxDynamicSharedMemorySize, SMEM_128_64);

    const dim3 blk(256);
    const dim3 tblk(32, 8);

    // 0) activation + attention-weight conversions (launches 0..4)
    conv16<<<(NTOK * Dc / 4 + 255) / 256, 256>>>(hidden, hid16, NTOK * Dc / 4);
    tconv<<<dim3(Dc / 32, Dc / 32, 1), tblk>>>(wq, wqT, Dc, Dc);
    tconv<<<dim3(Dc / 32, Dc / 32, 1), tblk>>>(wk, wkT, Dc, Dc);
    tconv<<<dim3(Dc / 32, Dc / 32, 1), tblk>>>(wv, wvT, Dc, Dc);
    tconv<<<dim3(Dc / 32, Dc / 32, 1), tblk>>>(wo, woT, Dc, Dc);

    // 1) Q/K projections -> fp16; V projection -> vT (transposed scatter)
    //    (launch index 5 = Q gemm -> gets captured by ncu -s 5)
    {
        dim3 grid(Dc / 128, NTOK / 256, 1);
        hgemm<256,128,6><<<grid, blk, SMEM_256_128>>>(hid16, wqT, nullptr, q16, bq, nullptr,
            Dc, Dc, Dc, Dc, 0, 0.f, 1, 0,0,0,0,0,0,0);
        hgemm<256,128,6><<<grid, blk, SMEM_256_128>>>(hid16, wkT, nullptr, k16, bk, nullptr,
            Dc, Dc, Dc, Dc, 0, 0.f, 1, 0,0,0,0,0,0,0);
        hgemm<256,128,7><<<grid, blk, SMEM_256_128>>>(hid16, wvT, nullptr, vT16, bv, nullptr,
            Dc, Dc, Dc, Dc, 0, 0.f, 1, 0,0,0,0,0,0,0);
    }

    // 2) scores = QK^T/8 + mask (per b,h; K=64)
    {
        dim3 grid(Sc / 128, Sc / 256, Bc * Hc);
        hgemm<256,128,3><<<grid, blk, SMEM_256_128>>>(q16, k16, scores, nullptr, nullptr, mask,
            DHc, Dc, Dc, Sc, Sc, 0.125f, Hc,
            (long long)Sc * Dc, DHc,
            (long long)Sc * Dc, DHc,
            (long long)Hc * Sc * Sc, (long long)Sc * Sc,
            (long long)Sc * Sc);
    }

    // 3) softmax -> fp16 probs
    softmax2048<<<Bc * Hc * Sc, 256>>>(scores, pr16);

    // 4) ctx = probs @ V   (B operand = vT [DH,S] rows, N=64 per head)
    {
        dim3 grid(1, Sc / 128, Bc * Hc);
        hgemm<128,64,6><<<grid, blk, SMEM_128_64>>>(pr16, vT16, nullptr, ctx16, nullptr, nullptr,
            Sc, Sc, Sc, Dc, 0, 0.f, Hc,
            (long long)Hc * Sc * Sc, (long long)Sc * Sc,
            (long long)Hc * DHc * Sc, (long long)DHc * Sc,
            (long long)Sc * Dc, (long long)DHc, 0);
    }

    // 5) output projection -> fp32 attn
    {
        dim3 grid(Dc / 128, NTOK / 256, 1);
        hgemm<256,128,0><<<grid, blk, SMEM_256_128>>>(ctx16, woT, attn, nullptr, bo, nullptr,
            Dc, Dc, Dc, Dc, 0, 0.f, 1, 0,0,0,0,0,0,0);
    }

    // MoE weight conversions (deferred; only needed from step 8 on)
    tconv<<<dim3(Fc / 32, Dc / 32, Ec), tblk>>>(w1, w1T, Dc, Fc);
    tconv<<<dim3(Dc / 32, Fc / 32, Ec), tblk>>>(w2, w2T, Fc, Dc);

    // 6) inter = LN1(attn + hidden)  (fp32 + fp16)
    ln_residual<<<NTOK, 256>>>(attn, hidden, ln1_g, ln1_b, inter, int16_);

    // 7) gate
    gate_kernel<<<NTOK, 256>>>(inter, gate_w, gate_b, gate, gate_out);

    // 8) MoE
    for (int e = 0; e < Ec; e++) {
        dim3 gh(Fc / 128, NTOK / 256, 1);
        hgemm<256,128,1><<<gh, blk, SMEM_256_128>>>(int16_, w1T + (size_t)e * Dc * Fc,
            nullptr, h16, b1 + (size_t)e * Fc, nullptr,
            Dc, Dc, Dc, Fc, 0, 0.f, 1, 0,0,0,0,0,0,0);

        dim3 gy(Dc / 128, NTOK / 256, 1);
        if (e == 0)
            hgemm<256,128,2><<<gy, blk, SMEM_256_128>>>(h16, w2T + (size_t)e * Fc * Dc,
                moe, nullptr, b2 + (size_t)e * Dc, gate + e,
                Fc, Fc, Fc, Dc, Ec, 0.f, 1, 0,0,0,0,0,0,0);
        else
            hgemm<256,128,5><<<gy, blk, SMEM_256_128>>>(h16, w2T + (size_t)e * Fc * Dc,
                moe, nullptr, b2 + (size_t)e * Dc, gate + e,
                Fc, Fc, Fc, Dc, Ec, 0.f, 1, 0,0,0,0,0,0,0);
    }

    // 9) output = LN2(moe + inter)
    ln_residual<<<NTOK, 256>>>(moe, inter, ln2_g, ln2_b, out, nullptr);
}

// round 6
// speedup vs baseline: 1.3369x; 1.3369x over previous
#include <cuda_runtime.h>
#include <cuda_fp16.h>
#include <math.h>
#include <stdint.h>

// ---------------- problem constants ----------------
#define Bc 2
#define Sc 2048
#define Dc 1024
#define Hc 16
#define DHc 64
#define Fc 4096
#define Ec 8
#define NTOK (Bc * Sc)
#define LN_EPS 1e-6f

// ---------------- fp32 scratch ----------------
static const size_t F_ATTN  = 0;
static const size_t F_INT   = F_ATTN + (size_t)NTOK * Dc;
static const size_t F_MOE   = F_INT  + (size_t)NTOK * Dc;
static const size_t F_GATE  = F_MOE  + (size_t)NTOK * Dc;
static const size_t F_QKVB  = F_GATE + (size_t)NTOK * Ec;
static const size_t F_TOTAL = F_QKVB + 3 * (size_t)Dc;
__device__ float g_f32[F_TOTAL];

// ---------------- fp16 scratch ----------------
static const size_t H_HID  = 0;
static const size_t H_Q    = H_HID + (size_t)NTOK * Dc;
static const size_t H_K    = H_Q   + (size_t)NTOK * Dc;     // contiguous with Q
static const size_t H_VT   = H_K   + (size_t)NTOK * Dc;     // [B,H,DH,S], contiguous with K
static const size_t H_CTX  = H_VT  + (size_t)NTOK * Dc;
static const size_t H_INT  = H_CTX + (size_t)NTOK * Dc;
static const size_t H_SC   = H_INT + (size_t)NTOK * Dc;                 // fp16 scores/probs (in-place)
static const size_t H_HB   = H_SC  + (size_t)Bc * Hc * Sc * Sc;         // 8 * NTOK * Fc
static const size_t H_P2   = H_HB  + (size_t)Ec * NTOK * Fc;            // 8 * NTOK * Dc partials
static const size_t H_WQ   = H_P2  + (size_t)Ec * NTOK * Dc;
static const size_t H_WK   = H_WQ  + (size_t)Dc * Dc;
static const size_t H_WV   = H_WK  + (size_t)Dc * Dc;
static const size_t H_WO   = H_WV  + (size_t)Dc * Dc;
static const size_t H_W1   = H_WO  + (size_t)Dc * Dc;       // [E][N=F,K=D]
static const size_t H_W2   = H_W1  + (size_t)Ec * Dc * Fc;  // [E][N=D,K=F]
static const size_t H_TOTAL= H_W2  + (size_t)Ec * Fc * Dc;
__device__ __half g_f16[H_TOTAL];

// ---------------- PTX helpers ----------------
__device__ __forceinline__ uint32_t smem_u32(const void* p) {
    uint32_t a;
    asm("{ .reg .u64 t; cvta.to.shared.u64 t, %1; cvt.u32.u64 %0, t; }" : "=r"(a) : "l"(p));
    return a;
}
__device__ __forceinline__ void cp16(uint32_t s, const void* g) {
    asm volatile("cp.async.cg.shared.global [%0], [%1], 16;" :: "r"(s), "l"(g));
}
#define CP_COMMIT() asm volatile("cp.async.commit_group;" ::: "memory")
#define CP_WAIT(n)  asm volatile("cp.async.wait_group %0;" :: "n"(n) : "memory")

__device__ __forceinline__ void ldm_x4(uint32_t* r, uint32_t addr) {
    asm volatile("ldmatrix.sync.aligned.m8n8.x4.shared.b16 {%0,%1,%2,%3}, [%4];"
        : "=r"(r[0]), "=r"(r[1]), "=r"(r[2]), "=r"(r[3]) : "r"(addr));
}
__device__ __forceinline__ void mma16816(float* c, const uint32_t* a, const uint32_t* b) {
    asm volatile(
        "mma.sync.aligned.m16n8k16.row.col.f32.f16.f16.f32 "
        "{%0,%1,%2,%3}, {%4,%5,%6,%7}, {%8,%9}, {%0,%1,%2,%3};"
        : "+f"(c[0]), "+f"(c[1]), "+f"(c[2]), "+f"(c[3])
        : "r"(a[0]), "r"(a[1]), "r"(a[2]), "r"(a[3]), "r"(b[0]), "r"(b[1]));
}

__device__ __forceinline__ float gelu_tanh(float x) {
    float x3 = x * x * x;
    float t  = tanhf(0.7978845608028654f * (x + 0.044715f * x3));
    return 0.5f * x * (1.0f + t);
}
__device__ __forceinline__ uint32_t pack_h2(float a, float b) {
    __half2 h = __floats2half2_rn(a, b);
    return *reinterpret_cast<uint32_t*>(&h);
}

// ============================================================================
// HMMA GEMM: C[MT,NT tiles] = A[M,K] * B[N,K]^T   (fp16 K-major operands)
// CTA 128 x NT, BK=32, 8 warps (4M x 2N), warp tile 32 x NT/2, 4-stage cp.async.
// EPI: 0 = fp32 C = acc + bias?
//      1 = fp16 C16 = gelu(acc + bias)
//      3 = fp16 C16 = acc*alpha + mask          (scores)
//      6 = fp16 C16 = acc + bias?
//      9 = QKV route: hh<2 plain fp16; hh==2 V^T scatter
// Batched over blockIdx.z (bb = z/Hdim, hh = z%Hdim); bias += hh*biasOH.
// ============================================================================
#define SPAD 40
#define STAGES 4

template <int NT, int EPI>
__global__ __launch_bounds__(256)
void hgemm(const __half* __restrict__ A, const __half* __restrict__ B,
           float* __restrict__ C, __half* __restrict__ C16,
           const float* __restrict__ bias, const float* __restrict__ aux,
           int K, int lda, int ldb, int ldc, int ldaux, float alpha, int Hdim,
           long long aOB, long long aOH, long long bOB, long long bOH,
           long long cOB, long long cOH, long long xOB, long long biasOH)
{
    extern __shared__ __half smem[];

    const int tid = threadIdx.x, wid = tid >> 5, lane = tid & 31;
    const int wm = wid & 3, wn = wid >> 2;          // warp grid 4 x 2
    constexpr int WN = NT / 2;
    constexpr int NF = WN / 8;

    const int m0 = blockIdx.y * 128, n0 = blockIdx.x * NT;
    const int z = blockIdx.z, bb = z / Hdim, hh = z - bb * Hdim;
    A += (size_t)bb * aOB + (size_t)hh * aOH;
    B += (size_t)bb * bOB + (size_t)hh * bOH;
    if (bias) bias += (size_t)hh * biasOH;
    const long long coff = (long long)bb * cOB + (long long)hh * cOH;

    const uint32_t ABUF = 128 * SPAD * 2;
    const uint32_t BBUF = (uint32_t)NT * SPAD * 2;
    const uint32_t abase = smem_u32(smem);
    const uint32_t bbase = abase + STAGES * ABUF;

    float acc[2][NF][4];
#pragma unroll
    for (int i = 0; i < 2; i++)
#pragma unroll
        for (int j = 0; j < NF; j++)
#pragma unroll
            for (int r = 0; r < 4; r++) acc[i][j][r] = 0.0f;

    const int nc = K >> 5;

    auto load_tile = [&](int c, int buf) {
        const __half* Ab = A + (size_t)m0 * lda + (size_t)c * 32;
#pragma unroll
        for (int it = 0; it < 2; it++) {
            int lin = it * 256 + tid;
            int row = lin >> 2, seg = lin & 3;
            cp16(abase + buf * ABUF + row * (SPAD * 2) + seg * 16,
                 Ab + (size_t)row * lda + seg * 8);
        }
        const __half* Bb = B + (size_t)n0 * ldb + (size_t)c * 32;
#pragma unroll
        for (int it = 0; it < NT / 64; it++) {
            int lin = it * 256 + tid;
            int row = lin >> 2, seg = lin & 3;
            cp16(bbase + buf * BBUF + row * (SPAD * 2) + seg * 16,
                 Bb + (size_t)row * ldb + seg * 8);
        }
    };

#pragma unroll
    for (int s = 0; s < STAGES - 1; s++) {
        if (s < nc) load_tile(s, s);
        CP_COMMIT();
    }

    for (int c = 0; c < nc; c++) {
        CP_WAIT(STAGES - 2);
        __syncthreads();
        const int nxt = c + STAGES - 1;
        if (nxt < nc) load_tile(nxt, nxt % STAGES);
        CP_COMMIT();

        const int buf = c % STAGES;
        const uint32_t ab = abase + buf * ABUF;
        const uint32_t bbf = bbase + buf * BBUF;

#pragma unroll
        for (int ks = 0; ks < 2; ks++) {
            uint32_t af[2][4];
#pragma unroll
            for (int mi = 0; mi < 2; mi++) {
                int row = wm * 32 + mi * 16 + (lane & 15);
                int col = ks * 16 + (lane >> 4) * 8;
                ldm_x4(af[mi], ab + row * (SPAD * 2) + col * 2);
            }
            uint32_t bf[NF][2];
#pragma unroll
            for (int p = 0; p < NF / 2; p++) {
                int row = wn * WN + p * 16 + (lane & 7) + ((lane >> 4) << 3);
                int col = ks * 16 + ((lane >> 3) & 1) * 8;
                uint32_t t[4];
                ldm_x4(t, bbf + row * (SPAD * 2) + col * 2);
                bf[2 * p][0] = t[0]; bf[2 * p][1] = t[1];
                bf[2 * p + 1][0] = t[2]; bf[2 * p + 1][1] = t[3];
            }
#pragma unroll
            for (int mi = 0; mi < 2; mi++)
#pragma unroll
                for (int nj = 0; nj < NF; nj++)
                    mma16816(acc[mi][nj], af[mi], bf[nj]);
        }
    }

    // -------- epilogue --------
#pragma unroll
    for (int mi = 0; mi < 2; mi++) {
#pragma unroll
        for (int nj = 0; nj < NF; nj++) {
            const int r0 = m0 + wm * 32 + mi * 16 + (lane >> 2);
            const int cc = n0 + wn * WN + nj * 8 + (lane & 3) * 2;
#pragma unroll
            for (int h = 0; h < 2; h++) {
                const int row = r0 + h * 8;
                const float v0 = acc[mi][nj][2 * h + 0];
                const float v1 = acc[mi][nj][2 * h + 1];
                if (EPI == 0) {
                    float b0 = bias ? bias[cc] : 0.f, b1 = bias ? bias[cc + 1] : 0.f;
                    float2 o = make_float2(v0 + b0, v1 + b1);
                    *(float2*)(C + coff + (size_t)row * ldc + cc) = o;
                } else if (EPI == 3) {
                    const float* mp = aux + (size_t)bb * xOB + (size_t)row * ldaux + cc;
                    *(uint32_t*)(C16 + coff + (size_t)row * ldc + cc) =
                        pack_h2(v0 * alpha + mp[0], v1 * alpha + mp[1]);
                } else if (EPI == 1 || EPI == 6) {
                    float o0 = v0 + (bias ? bias[cc] : 0.f);
                    float o1 = v1 + (bias ? bias[cc + 1] : 0.f);
                    if (EPI == 1) { o0 = gelu_tanh(o0); o1 = gelu_tanh(o1); }
                    *(uint32_t*)(C16 + coff + (size_t)row * ldc + cc) = pack_h2(o0, o1);
                } else if (EPI == 9) {
                    float o0 = v0 + bias[cc];
                    float o1 = v1 + bias[cc + 1];
                    if (hh < 2) {
                        *(uint32_t*)(C16 + coff + (size_t)row * ldc + cc) = pack_h2(o0, o1);
                    } else {
                        const int b_ = row >> 11, s_ = row & 2047;
                        const int h0 = cc >> 6, d0 = cc & 63;
                        const int h1 = (cc + 1) >> 6, d1 = (cc + 1) & 63;
                        C16[coff + ((size_t)((b_ * Hc + h0) * DHc + d0)) * Sc + s_] = __float2half(o0);
                        C16[coff + ((size_t)((b_ * Hc + h1) * DHc + d1)) * Sc + s_] = __float2half(o1);
                    }
                }
            }
        }
    }
}

static const int SMEM_NT128 = STAGES * (128 + 128) * SPAD * 2;  // 81920
static const int SMEM_NT64  = STAGES * (128 + 64) * SPAD * 2;   // 61440

// ---------------- small kernels ----------------
__global__ void conv16(const float* __restrict__ s, __half* __restrict__ d, int n4)
{
    int i = blockIdx.x * blockDim.x + threadIdx.x;
    if (i < n4) {
        float4 v = ((const float4*)s)[i];
        uint2 u;
        u.x = pack_h2(v.x, v.y); u.y = pack_h2(v.z, v.w);
        ((uint2*)d)[i] = u;
    }
}

__global__ void pack3(const float* __restrict__ a, const float* __restrict__ b,
                      const float* __restrict__ c, float* __restrict__ dst)
{
    int i = blockIdx.x * blockDim.x + threadIdx.x;
    if (i < Dc) { dst[i] = a[i]; dst[Dc + i] = b[i]; dst[2 * Dc + i] = c[i]; }
}

// transpose-convert: src [K,N] f32 -> dst [N,K] f16
__global__ void tconv(const float* __restrict__ src, __half* __restrict__ dst, int K, int N)
{
    __shared__ float t[32][33];
    src += (size_t)blockIdx.z * K * N;
    dst += (size_t)blockIdx.z * K * N;
    const int k0 = blockIdx.y * 32, n0 = blockIdx.x * 32;
    const int x = threadIdx.x, y = threadIdx.y;
#pragma unroll
    for (int i = 0; i < 32; i += 8)
        t[y + i][x] = src[(size_t)(k0 + y + i) * N + n0 + x];
    __syncthreads();
#pragma unroll
    for (int i = 0; i < 32; i += 8)
        dst[(size_t)(n0 + y + i) * K + k0 + x] = __float2half(t[x][y + i]);
}

// in-place fp16 softmax over rows of 2048
__global__ void softmax2048h(__half* __restrict__ data)
{
    __shared__ float red[256];
    __half2* row = (__half2*)data + (size_t)blockIdx.x * 1024;
    const int tid = threadIdx.x;
    float v[8];
    float mx = -INFINITY;
#pragma unroll
    for (int i = 0; i < 4; i++) {
        float2 f = __half22float2(row[tid + i * 256]);
        v[2 * i] = f.x; v[2 * i + 1] = f.y;
        mx = fmaxf(mx, fmaxf(f.x, f.y));
    }
    red[tid] = mx; __syncthreads();
    for (int s = 128; s > 0; s >>= 1) { if (tid < s) red[tid] = fmaxf(red[tid], red[tid + s]); __syncthreads(); }
    mx = red[0]; __syncthreads();
    float sum = 0.f;
#pragma unroll
    for (int i = 0; i < 8; i++) { v[i] = expf(v[i] - mx); sum += v[i]; }
    red[tid] = sum; __syncthreads();
    for (int s = 128; s > 0; s >>= 1) { if (tid < s) red[tid] += red[tid + s]; __syncthreads(); }
    const float inv = 1.0f / red[0];
#pragma unroll
    for (int i = 0; i < 4; i++)
        row[tid + i * 256] = __floats2half2_rn(v[2 * i] * inv, v[2 * i + 1] * inv);
}

// LayerNorm(x + r), fp32 out + optional fp16 copy
__global__ void ln_residual(const float* __restrict__ x, const float* __restrict__ r,
                            const float* __restrict__ g, const float* __restrict__ b,
                            float* __restrict__ out, __half* __restrict__ out16)
{
    __shared__ float red[256];
    const size_t base = (size_t)blockIdx.x * Dc;
    const int tid = threadIdx.x;
    float v[4]; float s = 0.f;
#pragma unroll
    for (int i = 0; i < 4; i++) { const int c = tid + i * 256; v[i] = x[base + c] + r[base + c]; s += v[i]; }
    red[tid] = s; __syncthreads();
    for (int st = 128; st > 0; st >>= 1) { if (tid < st) red[tid] += red[tid + st]; __syncthreads(); }
    const float mean = red[0] * (1.0f / Dc); __syncthreads();
    float ss = 0.f;
#pragma unroll
    for (int i = 0; i < 4; i++) { const float d = v[i] - mean; ss += d * d; }
    red[tid] = ss; __syncthreads();
    for (int st = 128; st > 0; st >>= 1) { if (tid < st) red[tid] += red[tid + st]; __syncthreads(); }
    const float rstd = rsqrtf(red[0] * (1.0f / Dc) + LN_EPS);
#pragma unroll
    for (int i = 0; i < 4; i++) {
        const int c = tid + i * 256;
        const float o = (v[i] - mean) * rstd * g[c] + b[c];
        out[base + c] = o;
        if (out16) out16[base + c] = __float2half(o);
    }
}

// gate: softmax(x @ gate_w + gate_b) over E=8
__global__ void gate_kernel(const float* __restrict__ x, const float* __restrict__ gw,
                            const float* __restrict__ gb,
                            float* __restrict__ gate, float* __restrict__ gate_out)
{
    const int m = blockIdx.x;
    const int tid = threadIdx.x;
    const int wid = tid >> 5, lane = tid & 31;
    __shared__ float logits[Ec];
    float s = 0.f;
    const float* xr = x + (size_t)m * Dc;
    for (int d = lane; d < Dc; d += 32) s += xr[d] * gw[d * Ec + wid];
#pragma unroll
    for (int o = 16; o > 0; o >>= 1) s += __shfl_down_sync(0xffffffffu, s, o);
    if (lane == 0) logits[wid] = s + gb[wid];
    __syncthreads();
    if (tid == 0) {
        float mx = logits[0];
#pragma unroll
        for (int e = 1; e < Ec; e++) mx = fmaxf(mx, logits[e]);
        float p[Ec]; float sum = 0.f;
#pragma unroll
        for (int e = 0; e < Ec; e++) { p[e] = expf(logits[e] - mx); sum += p[e]; }
        const float inv = 1.0f / sum;
#pragma unroll
        for (int e = 0; e < Ec; e++) {
            const float pv = p[e] * inv;
            gate[(size_t)m * Ec + e] = pv;
            if (gate_out) gate_out[(size_t)m * Ec + e] = pv;
        }
    }
}

// gate-weighted reduce of per-expert fp16 partials -> fp32 moe
__global__ void moe_reduce(const __half* __restrict__ part, const float* __restrict__ gate,
                           float* __restrict__ outm)
{
    const int i = blockIdx.x * blockDim.x + threadIdx.x;     // over NTOK*Dc/2
    const int m = i / (Dc / 2);
    const float* gm = gate + (size_t)m * Ec;
    float2 s = make_float2(0.f, 0.f);
#pragma unroll
    for (int e = 0; e < Ec; e++) {
        float2 f = __half22float2(((const __half2*)part)[(size_t)e * (NTOK * Dc / 2) + i]);
        const float g = gm[e];
        s.x += g * f.x; s.y += g * f.y;
    }
    ((float2*)outm)[i] = s;
}

// ---------------- launch ----------------------------------------------------
extern "C" void kernel_launch(void* const* d_in, const int* in_sizes, int n_in,
                              void* d_out, int out_size)
{
    const float* hidden = (const float*)d_in[0];
    const float* mask   = (const float*)d_in[1];
    const float* wq = (const float*)d_in[2];  const float* bq = (const float*)d_in[3];
    const float* wk = (const float*)d_in[4];  const float* bk = (const float*)d_in[5];
    const float* wv = (const float*)d_in[6];  const float* bv = (const float*)d_in[7];
    const float* wo = (const float*)d_in[8];  const float* bo = (const float*)d_in[9];
    const float* ln1_g = (const float*)d_in[10]; const float* ln1_b = (const float*)d_in[11];
    const float* gate_w = (const float*)d_in[12]; const float* gate_b = (const float*)d_in[13];
    const float* w1 = (const float*)d_in[14]; const float* b1 = (const float*)d_in[15];
    const float* w2 = (const float*)d_in[16]; const float* b2 = (const float*)d_in[17];
    const float* ln2_g = (const float*)d_in[18]; const float* ln2_b = (const float*)d_in[19];

    float* f32 = nullptr;  __half* f16 = nullptr;
    cudaGetSymbolAddress((void**)&f32, g_f32);
    cudaGetSymbolAddress((void**)&f16, g_f16);

    float*  attn   = f32 + F_ATTN;
    float*  inter  = f32 + F_INT;
    float*  moe    = f32 + F_MOE;
    float*  gate   = f32 + F_GATE;
    float*  qkvb   = f32 + F_QKVB;
    __half* hid16  = f16 + H_HID;
    __half* q16    = f16 + H_Q;
    __half* vT16   = f16 + H_VT;
    __half* ctx16  = f16 + H_CTX;
    __half* int16_ = f16 + H_INT;
    __half* sc16   = f16 + H_SC;
    __half* h16    = f16 + H_HB;
    __half* p2     = f16 + H_P2;
    __half* wqT = f16 + H_WQ; __half* wkT = f16 + H_WK;
    __half* wvT = f16 + H_WV; __half* woT = f16 + H_WO;
    __half* w1T = f16 + H_W1; __half* w2T = f16 + H_W2;

    float* out = (float*)d_out;
    float* gate_out = nullptr;
    if ((size_t)out_size >= (size_t)NTOK * Dc + (size_t)NTOK * Ec)
        gate_out = out + (size_t)NTOK * Dc;

    cudaFuncSetAttribute(hgemm<128,0>, cudaFuncAttributeMaxDynamicSharedMemorySize, SMEM_NT128);
    cudaFuncSetAttribute(hgemm<128,1>, cudaFuncAttributeMaxDynamicSharedMemorySize, SMEM_NT128);
    cudaFuncSetAttribute(hgemm<128,3>, cudaFuncAttributeMaxDynamicSharedMemorySize, SMEM_NT128);
    cudaFuncSetAttribute(hgemm<128,6>, cudaFuncAttributeMaxDynamicSharedMemorySize, SMEM_NT128);
    cudaFuncSetAttribute(hgemm<128,9>, cudaFuncAttributeMaxDynamicSharedMemorySize, SMEM_NT128);
    cudaFuncSetAttribute(hgemm<64,6>,  cudaFuncAttributeMaxDynamicSharedMemorySize, SMEM_NT64);

    const dim3 blk(256);
    const dim3 tblk(32, 8);

    // 0-4) conversions + bias pack
    pack3<<<4, 256>>>(bq, bk, bv, qkvb);
    conv16<<<(NTOK * Dc / 4 + 255) / 256, 256>>>(hidden, hid16, NTOK * Dc / 4);
    tconv<<<dim3(Dc / 32, Dc / 32, 1), tblk>>>(wq, wqT, Dc, Dc);
    tconv<<<dim3(Dc / 32, Dc / 32, 1), tblk>>>(wk, wkT, Dc, Dc);
    tconv<<<dim3(Dc / 32, Dc / 32, 1), tblk>>>(wv, wvT, Dc, Dc);

    // 5) fused Q/K/V projection (z = 0,1,2 -> q16, k16, vT scatter)
    {
        dim3 grid(Dc / 128, NTOK / 128, 3);
        hgemm<128,9><<<grid, blk, SMEM_NT128>>>(hid16, wqT, nullptr, q16, qkvb, nullptr,
            Dc, Dc, Dc, Dc, 0, 0.f, 3,
            0, 0,                                   // A same for all z
            0, (long long)Dc * Dc,                  // B per z
            0, (long long)NTOK * Dc,                // C per z
            0, (long long)Dc);                      // bias per z
    }

    tconv<<<dim3(Dc / 32, Dc / 32, 1), tblk>>>(wo, woT, Dc, Dc);

    // 6) scores (fp16) = QK^T/8 + mask, per (b,h)
    {
        dim3 grid(Sc / 128, Sc / 128, Bc * Hc);
        hgemm<128,3><<<grid, blk, SMEM_NT128>>>(q16, q16 + (size_t)NTOK * Dc, nullptr, sc16,
            nullptr, mask,
            DHc, Dc, Dc, Sc, Sc, 0.125f, Hc,
            (long long)Sc * Dc, DHc,
            (long long)Sc * Dc, DHc,
            (long long)Hc * Sc * Sc, (long long)Sc * Sc,
            (long long)Sc * Sc, 0);
    }

    // 7) in-place fp16 softmax
    softmax2048h<<<Bc * Hc * Sc, 256>>>(sc16);

    // 8) ctx = probs @ V   (B operand = vT [DH,S], N=64 per head)
    {
        dim3 grid(1, Sc / 128, Bc * Hc);
        hgemm<64,6><<<grid, blk, SMEM_NT64>>>(sc16, vT16, nullptr, ctx16, nullptr, nullptr,
            Sc, Sc, Sc, Dc, 0, 0.f, Hc,
            (long long)Hc * Sc * Sc, (long long)Sc * Sc,
            (long long)Hc * DHc * Sc, (long long)DHc * Sc,
            (long long)Sc * Dc, (long long)DHc, 0, 0);
    }

    // 9) output projection -> fp32 attn
    {
        dim3 grid(Dc / 128, NTOK / 128, 1);
        hgemm<128,0><<<grid, blk, SMEM_NT128>>>(ctx16, woT, attn, nullptr, bo, nullptr,
            Dc, Dc, Dc, Dc, 0, 0.f, 1, 0,0,0,0,0,0,0,0);
    }

    // MoE weight conversions (deferred)
    tconv<<<dim3(Fc / 32, Dc / 32, Ec), tblk>>>(w1, w1T, Dc, Fc);
    tconv<<<dim3(Dc / 32, Fc / 32, Ec), tblk>>>(w2, w2T, Fc, Dc);

    // 10) inter = LN1(attn + hidden)
    ln_residual<<<NTOK, 256>>>(attn, hidden, ln1_g, ln1_b, inter, int16_);

    // 11) gate
    gate_kernel<<<NTOK, 256>>>(inter, gate_w, gate_b, gate, gate_out);

    // 12) MoE batched across experts (z = expert)
    {
        dim3 gh(Fc / 128, NTOK / 128, Ec);
        hgemm<128,1><<<gh, blk, SMEM_NT128>>>(int16_, w1T, nullptr, h16, b1, nullptr,
            Dc, Dc, Dc, Fc, 0, 0.f, Ec,
            0, 0,
            0, (long long)Dc * Fc,
            0, (long long)NTOK * Fc,
            0, (long long)Fc);

        dim3 gy(Dc / 128, NTOK / 128, Ec);
        hgemm<128,6><<<gy, blk, SMEM_NT128>>>(h16, w2T, nullptr, p2, b2, nullptr,
            Fc, Fc, Fc, Dc, 0, 0.f, Ec,
            0, (long long)NTOK * Fc,
            0, (long long)Fc * Dc,
            0, (long long)NTOK * Dc,
            0, (long long)Dc);
    }

    // 13) gate-weighted reduce
    moe_reduce<<<NTOK * Dc / 2 / 256, 256>>>(p2, gate, moe);

    // 14) output = LN2(moe + inter)
    ln_residual<<<NTOK, 256>>>(moe, inter, ln2_g, ln2_b, out, nullptr);
}

// round 7
// speedup vs baseline: 1.4214x; 1.0632x over previous
#include <cuda_runtime.h>
#include <cuda_fp16.h>
#include <math.h>
#include <stdint.h>

// ---------------- problem constants ----------------
#define Bc 2
#define Sc 2048
#define Dc 1024
#define Hc 16
#define DHc 64
#define Fc 4096
#define Ec 8
#define NTOK (Bc * Sc)
#define LN_EPS 1e-6f

// ---------------- fp32 scratch ----------------
static const size_t F_ATTN  = 0;
static const size_t F_INT   = F_ATTN + (size_t)NTOK * Dc;
static const size_t F_MOE   = F_INT  + (size_t)NTOK * Dc;
static const size_t F_GATE  = F_MOE  + (size_t)NTOK * Dc;
static const size_t F_QKVB  = F_GATE + (size_t)NTOK * Ec;
static const size_t F_TOTAL = F_QKVB + 3 * (size_t)Dc;
__device__ float g_f32[F_TOTAL];

// ---------------- fp16 scratch ----------------
static const size_t H_HID  = 0;
static const size_t H_Q    = H_HID + (size_t)NTOK * Dc;
static const size_t H_K    = H_Q   + (size_t)NTOK * Dc;     // contiguous with Q
static const size_t H_VT   = H_K   + (size_t)NTOK * Dc;     // [B,H,DH,S]
static const size_t H_CTX  = H_VT  + (size_t)NTOK * Dc;
static const size_t H_INT  = H_CTX + (size_t)NTOK * Dc;
static const size_t H_SC   = H_INT + (size_t)NTOK * Dc;                 // fp16 scores/probs
static const size_t H_HB   = H_SC  + (size_t)Bc * Hc * Sc * Sc;
static const size_t H_P2   = H_HB  + (size_t)Ec * NTOK * Fc;
static const size_t H_WQ   = H_P2  + (size_t)Ec * NTOK * Dc;
static const size_t H_WK   = H_WQ  + (size_t)Dc * Dc;
static const size_t H_WV   = H_WK  + (size_t)Dc * Dc;
static const size_t H_WO   = H_WV  + (size_t)Dc * Dc;
static const size_t H_W1   = H_WO  + (size_t)Dc * Dc;       // [E][N=F,K=D]
static const size_t H_W2   = H_W1  + (size_t)Ec * Dc * Fc;  // [E][N=D,K=F]
static const size_t H_TOTAL= H_W2  + (size_t)Ec * Fc * Dc;
__device__ __half g_f16[H_TOTAL];

// ---------------- PTX helpers ----------------
__device__ __forceinline__ uint32_t smem_u32(const void* p) {
    uint32_t a;
    asm("{ .reg .u64 t; cvta.to.shared.u64 t, %1; cvt.u32.u64 %0, t; }" : "=r"(a) : "l"(p));
    return a;
}
__device__ __forceinline__ void cp16(uint32_t s, const void* g) {
    asm volatile("cp.async.cg.shared.global [%0], [%1], 16;" :: "r"(s), "l"(g));
}
#define CP_COMMIT() asm volatile("cp.async.commit_group;" ::: "memory")
#define CP_WAIT(n)  asm volatile("cp.async.wait_group %0;" :: "n"(n) : "memory")

__device__ __forceinline__ void ldm_x4(uint32_t* r, uint32_t addr) {
    asm volatile("ldmatrix.sync.aligned.m8n8.x4.shared.b16 {%0,%1,%2,%3}, [%4];"
        : "=r"(r[0]), "=r"(r[1]), "=r"(r[2]), "=r"(r[3]) : "r"(addr));
}
__device__ __forceinline__ void mma16816(float* c, const uint32_t* a, const uint32_t* b) {
    asm volatile(
        "mma.sync.aligned.m16n8k16.row.col.f32.f16.f16.f32 "
        "{%0,%1,%2,%3}, {%4,%5,%6,%7}, {%8,%9}, {%0,%1,%2,%3};"
        : "+f"(c[0]), "+f"(c[1]), "+f"(c[2]), "+f"(c[3])
        : "r"(a[0]), "r"(a[1]), "r"(a[2]), "r"(a[3]), "r"(b[0]), "r"(b[1]));
}

__device__ __forceinline__ float gelu_tanh(float x) {
    float x3 = x * x * x;
    float t  = tanhf(0.7978845608028654f * (x + 0.044715f * x3));
    return 0.5f * x * (1.0f + t);
}
__device__ __forceinline__ uint32_t pack_h2(float a, float b) {
    __half2 h = __floats2half2_rn(a, b);
    return *reinterpret_cast<uint32_t*>(&h);
}

// ============================================================================
// HMMA GEMM: C[128,NT tiles] = A[M,K] * B[N,K]^T   (fp16 K-major operands)
// CTA 128 x NT, BK=64 (4 ks steps of K=16), 8 warps (4M x 2N), warp tile
// 32 x NT/2, 3-stage cp.async pipeline, ONE __syncthreads per 64-K chunk.
// EPI: 0 = fp32 C = acc + bias?
//      1 = fp16 C16 = gelu(acc + bias)
//      3 = fp16 C16 = acc*alpha + mask          (scores)
//      6 = fp16 C16 = acc + bias?
//      9 = QKV route: hh<2 plain fp16; hh==2 V^T scatter
// Batched over blockIdx.z (bb = z/Hdim, hh = z%Hdim); bias += hh*biasOH.
// ============================================================================
#define SPAD 72          // smem row stride in halves (144 bytes)
#define STAGES 3

template <int NT, int EPI>
__global__ __launch_bounds__(256)
void hgemm(const __half* __restrict__ A, const __half* __restrict__ B,
           float* __restrict__ C, __half* __restrict__ C16,
           const float* __restrict__ bias, const float* __restrict__ aux,
           int K, int lda, int ldb, int ldc, int ldaux, float alpha, int Hdim,
           long long aOB, long long aOH, long long bOB, long long bOH,
           long long cOB, long long cOH, long long xOB, long long biasOH)
{
    extern __shared__ __half smem[];

    const int tid = threadIdx.x, wid = tid >> 5, lane = tid & 31;
    const int wm = wid & 3, wn = wid >> 2;          // warp grid 4 x 2
    constexpr int WN = NT / 2;
    constexpr int NF = WN / 8;

    const int m0 = blockIdx.y * 128, n0 = blockIdx.x * NT;
    const int z = blockIdx.z, bb = z / Hdim, hh = z - bb * Hdim;
    A += (size_t)bb * aOB + (size_t)hh * aOH;
    B += (size_t)bb * bOB + (size_t)hh * bOH;
    if (bias) bias += (size_t)hh * biasOH;
    const long long coff = (long long)bb * cOB + (long long)hh * cOH;

    const uint32_t ABUF = 128 * SPAD * 2;
    const uint32_t BBUF = (uint32_t)NT * SPAD * 2;
    const uint32_t abase = smem_u32(smem);
    const uint32_t bbase = abase + STAGES * ABUF;

    // per-thread invariant ldmatrix offsets (bytes within a stage)
    const uint32_t a_off = (uint32_t)((wm * 32 + (lane & 15)) * (SPAD * 2) + ((lane >> 4) * 8) * 2);
    const uint32_t b_off = (uint32_t)((wn * WN + (lane & 7) + ((lane >> 4) << 3)) * (SPAD * 2)
                                      + (((lane >> 3) & 1) * 8) * 2);

    float acc[2][NF][4];
#pragma unroll
    for (int i = 0; i < 2; i++)
#pragma unroll
        for (int j = 0; j < NF; j++)
#pragma unroll
            for (int r = 0; r < 4; r++) acc[i][j][r] = 0.0f;

    const int nc = K >> 6;   // BK = 64

    auto load_tile = [&](int c, int buf) {
        const __half* Ab = A + (size_t)m0 * lda + (size_t)c * 64;
#pragma unroll
        for (int it = 0; it < 4; it++) {
            int lin = it * 256 + tid;
            int row = lin >> 3, seg = lin & 7;
            cp16(abase + buf * ABUF + row * (SPAD * 2) + seg * 16,
                 Ab + (size_t)row * lda + seg * 8);
        }
        const __half* Bb = B + (size_t)n0 * ldb + (size_t)c * 64;
#pragma unroll
        for (int it = 0; it < NT / 32; it++) {
            int lin = it * 256 + tid;
            int row = lin >> 3, seg = lin & 7;
            cp16(bbase + buf * BBUF + row * (SPAD * 2) + seg * 16,
                 Bb + (size_t)row * ldb + seg * 8);
        }
    };

#pragma unroll
    for (int s = 0; s < STAGES - 1; s++) {
        if (s < nc) load_tile(s, s);
        CP_COMMIT();
    }

    for (int c = 0; c < nc; c++) {
        CP_WAIT(STAGES - 2);
        __syncthreads();
        const int nxt = c + STAGES - 1;
        if (nxt < nc) load_tile(nxt, nxt % STAGES);
        CP_COMMIT();

        const int buf = c % STAGES;
        const uint32_t ab = abase + buf * ABUF + a_off;
        const uint32_t bbf = bbase + buf * BBUF + b_off;

#pragma unroll
        for (int ks = 0; ks < 4; ks++) {
            uint32_t af[2][4];
#pragma unroll
            for (int mi = 0; mi < 2; mi++)
                ldm_x4(af[mi], ab + mi * 16 * (SPAD * 2) + ks * 32);
            uint32_t bf[NF][2];
#pragma unroll
            for (int p = 0; p < NF / 2; p++) {
                uint32_t t[4];
                ldm_x4(t, bbf + p * 16 * (SPAD * 2) + ks * 32);
                bf[2 * p][0] = t[0]; bf[2 * p][1] = t[1];
                bf[2 * p + 1][0] = t[2]; bf[2 * p + 1][1] = t[3];
            }
#pragma unroll
            for (int mi = 0; mi < 2; mi++)
#pragma unroll
                for (int nj = 0; nj < NF; nj++)
                    mma16816(acc[mi][nj], af[mi], bf[nj]);
        }
    }

    // -------- epilogue --------
#pragma unroll
    for (int mi = 0; mi < 2; mi++) {
#pragma unroll
        for (int nj = 0; nj < NF; nj++) {
            const int r0 = m0 + wm * 32 + mi * 16 + (lane >> 2);
            const int cc = n0 + wn * WN + nj * 8 + (lane & 3) * 2;
#pragma unroll
            for (int h = 0; h < 2; h++) {
                const int row = r0 + h * 8;
                const float v0 = acc[mi][nj][2 * h + 0];
                const float v1 = acc[mi][nj][2 * h + 1];
                if (EPI == 0) {
                    float b0 = bias ? bias[cc] : 0.f, b1 = bias ? bias[cc + 1] : 0.f;
                    float2 o = make_float2(v0 + b0, v1 + b1);
                    *(float2*)(C + coff + (size_t)row * ldc + cc) = o;
                } else if (EPI == 3) {
                    const float* mp = aux + (size_t)bb * xOB + (size_t)row * ldaux + cc;
                    *(uint32_t*)(C16 + coff + (size_t)row * ldc + cc) =
                        pack_h2(v0 * alpha + mp[0], v1 * alpha + mp[1]);
                } else if (EPI == 1 || EPI == 6) {
                    float o0 = v0 + (bias ? bias[cc] : 0.f);
                    float o1 = v1 + (bias ? bias[cc + 1] : 0.f);
                    if (EPI == 1) { o0 = gelu_tanh(o0); o1 = gelu_tanh(o1); }
                    *(uint32_t*)(C16 + coff + (size_t)row * ldc + cc) = pack_h2(o0, o1);
                } else if (EPI == 9) {
                    float o0 = v0 + bias[cc];
                    float o1 = v1 + bias[cc + 1];
                    if (hh < 2) {
                        *(uint32_t*)(C16 + coff + (size_t)row * ldc + cc) = pack_h2(o0, o1);
                    } else {
                        const int b_ = row >> 11, s_ = row & 2047;
                        const int h0 = cc >> 6, d0 = cc & 63;
                        const int h1 = (cc + 1) >> 6, d1 = (cc + 1) & 63;
                        C16[coff + ((size_t)((b_ * Hc + h0) * DHc + d0)) * Sc + s_] = __float2half(o0);
                        C16[coff + ((size_t)((b_ * Hc + h1) * DHc + d1)) * Sc + s_] = __float2half(o1);
                    }
                }
            }
        }
    }
}

static const int SMEM_NT128 = STAGES * (128 + 128) * SPAD * 2;  // 110592
static const int SMEM_NT64  = STAGES * (128 + 64) * SPAD * 2;   // 82944

// ---------------- small kernels ----------------
// fp32->fp16 convert of hidden + QKV bias pack, one launch
__global__ void convpack(const float* __restrict__ s, __half* __restrict__ d,
                         const float* __restrict__ bq, const float* __restrict__ bk,
                         const float* __restrict__ bv, float* __restrict__ qkvb)
{
    int i = blockIdx.x * blockDim.x + threadIdx.x;
    if (i < NTOK * Dc / 4) {
        float4 v = ((const float4*)s)[i];
        uint2 u;
        u.x = pack_h2(v.x, v.y); u.y = pack_h2(v.z, v.w);
        ((uint2*)d)[i] = u;
    }
    if (i < Dc) { qkvb[i] = bq[i]; qkvb[Dc + i] = bk[i]; qkvb[2 * Dc + i] = bv[i]; }
}

// ALL weight transposes in one launch: wq/wk/wv/wo (Dc x Dc), w1 (E x Dc x Fc),
// w2 (E x Fc x Dc). dstbase = f16 + H_WQ, layout contiguous.
__global__ void tconv_all(const float* __restrict__ wq, const float* __restrict__ wk,
                          const float* __restrict__ wv, const float* __restrict__ wo,
                          const float* __restrict__ w1, const float* __restrict__ w2,
                          __half* __restrict__ dstbase)
{
    __shared__ float t[32][33];
    int b = blockIdx.x;
    const float* src; __half* dst; int K, N;
    if (b < 4096) {
        int m = b >> 10; b &= 1023;
        src = (m == 0) ? wq : (m == 1) ? wk : (m == 2) ? wv : wo;
        dst = dstbase + (size_t)m * Dc * Dc; K = Dc; N = Dc;
    } else if (b < 4096 + 32768) {
        b -= 4096; int e = b >> 12; b &= 4095;
        src = w1 + (size_t)e * Dc * Fc;
        dst = dstbase + 4 * (size_t)Dc * Dc + (size_t)e * Dc * Fc; K = Dc; N = Fc;
    } else {
        b -= 36864; int e = b >> 12; b &= 4095;
        src = w2 + (size_t)e * Fc * Dc;
        dst = dstbase + 4 * (size_t)Dc * Dc + (size_t)Ec * Dc * Fc + (size_t)e * Fc * Dc;
        K = Fc; N = Dc;
    }
    const int ntx = N / 32;
    const int k0 = (b / ntx) * 32, n0 = (b % ntx) * 32;
    const int x = threadIdx.x, y = threadIdx.y;
#pragma unroll
    for (int i = 0; i < 32; i += 8)
        t[y + i][x] = src[(size_t)(k0 + y + i) * N + n0 + x];
    __syncthreads();
#pragma unroll
    for (int i = 0; i < 32; i += 8)
        dst[(size_t)(n0 + y + i) * K + k0 + x] = __float2half(t[x][y + i]);
}

// in-place fp16 softmax over rows of 2048
__global__ void softmax2048h(__half* __restrict__ data)
{
    __shared__ float red[256];
    __half2* row = (__half2*)data + (size_t)blockIdx.x * 1024;
    const int tid = threadIdx.x;
    float v[8];
    float mx = -INFINITY;
#pragma unroll
    for (int i = 0; i < 4; i++) {
        float2 f = __half22float2(row[tid + i * 256]);
        v[2 * i] = f.x; v[2 * i + 1] = f.y;
        mx = fmaxf(mx, fmaxf(f.x, f.y));
    }
    red[tid] = mx; __syncthreads();
    for (int s = 128; s > 0; s >>= 1) { if (tid < s) red[tid] = fmaxf(red[tid], red[tid + s]); __syncthreads(); }
    mx = red[0]; __syncthreads();
    float sum = 0.f;
#pragma unroll
    for (int i = 0; i < 8; i++) { v[i] = expf(v[i] - mx); sum += v[i]; }
    red[tid] = sum; __syncthreads();
    for (int s = 128; s > 0; s >>= 1) { if (tid < s) red[tid] += red[tid + s]; __syncthreads(); }
    const float inv = 1.0f / red[0];
#pragma unroll
    for (int i = 0; i < 4; i++)
        row[tid + i * 256] = __floats2half2_rn(v[2 * i] * inv, v[2 * i + 1] * inv);
}

// LayerNorm(x + r), fp32 out + optional fp16 copy
__global__ void ln_residual(const float* __restrict__ x, const float* __restrict__ r,
                            const float* __restrict__ g, const float* __restrict__ b,
                            float* __restrict__ out, __half* __restrict__ out16)
{
    __shared__ float red[256];
    const size_t base = (size_t)blockIdx.x * Dc;
    const int tid = threadIdx.x;
    float v[4]; float s = 0.f;
#pragma unroll
    for (int i = 0; i < 4; i++) { const int c = tid + i * 256; v[i] = x[base + c] + r[base + c]; s += v[i]; }
    red[tid] = s; __syncthreads();
    for (int st = 128; st > 0; st >>= 1) { if (tid < st) red[tid] += red[tid + st]; __syncthreads(); }
    const float mean = red[0] * (1.0f / Dc); __syncthreads();
    float ss = 0.f;
#pragma unroll
    for (int i = 0; i < 4; i++) { const float d = v[i] - mean; ss += d * d; }
    red[tid] = ss; __syncthreads();
    for (int st = 128; st > 0; st >>= 1) { if (tid < st) red[tid] += red[tid + st]; __syncthreads(); }
    const float rstd = rsqrtf(red[0] * (1.0f / Dc) + LN_EPS);
#pragma unroll
    for (int i = 0; i < 4; i++) {
        const int c = tid + i * 256;
        const float o = (v[i] - mean) * rstd * g[c] + b[c];
        out[base + c] = o;
        if (out16) out16[base + c] = __float2half(o);
    }
}

// gate: softmax(x @ gate_w + gate_b) over E=8
__global__ void gate_kernel(const float* __restrict__ x, const float* __restrict__ gw,
                            const float* __restrict__ gb,
                            float* __restrict__ gate, float* __restrict__ gate_out)
{
    const int m = blockIdx.x;
    const int tid = threadIdx.x;
    const int wid = tid >> 5, lane = tid & 31;
    __shared__ float logits[Ec];
    float s = 0.f;
    const float* xr = x + (size_t)m * Dc;
    for (int d = lane; d < Dc; d += 32) s += xr[d] * gw[d * Ec + wid];
#pragma unroll
    for (int o = 16; o > 0; o >>= 1) s += __shfl_down_sync(0xffffffffu, s, o);
    if (lane == 0) logits[wid] = s + gb[wid];
    __syncthreads();
    if (tid == 0) {
        float mx = logits[0];
#pragma unroll
        for (int e = 1; e < Ec; e++) mx = fmaxf(mx, logits[e]);
        float p[Ec]; float sum = 0.f;
#pragma unroll
        for (int e = 0; e < Ec; e++) { p[e] = expf(logits[e] - mx); sum += p[e]; }
        const float inv = 1.0f / sum;
#pragma unroll
        for (int e = 0; e < Ec; e++) {
            const float pv = p[e] * inv;
            gate[(size_t)m * Ec + e] = pv;
            if (gate_out) gate_out[(size_t)m * Ec + e] = pv;
        }
    }
}

// gate-weighted reduce of per-expert fp16 partials -> fp32 moe
__global__ void moe_reduce(const __half* __restrict__ part, const float* __restrict__ gate,
                           float* __restrict__ outm)
{
    const int i = blockIdx.x * blockDim.x + threadIdx.x;     // over NTOK*Dc/2
    const int m = i / (Dc / 2);
    const float* gm = gate + (size_t)m * Ec;
    float2 s = make_float2(0.f, 0.f);
#pragma unroll
    for (int e = 0; e < Ec; e++) {
        float2 f = __half22float2(((const __half2*)part)[(size_t)e * (NTOK * Dc / 2) + i]);
        const float g = gm[e];
        s.x += g * f.x; s.y += g * f.y;
    }
    ((float2*)outm)[i] = s;
}

// ---------------- launch ----------------------------------------------------
extern "C" void kernel_launch(void* const* d_in, const int* in_sizes, int n_in,
                              void* d_out, int out_size)
{
    const float* hidden = (const float*)d_in[0];
    const float* mask   = (const float*)d_in[1];
    const float* wq = (const float*)d_in[2];  const float* bq = (const float*)d_in[3];
    const float* wk = (const float*)d_in[4];  const float* bk = (const float*)d_in[5];
    const float* wv = (const float*)d_in[6];  const float* bv = (const float*)d_in[7];
    const float* wo = (const float*)d_in[8];  const float* bo = (const float*)d_in[9];
    const float* ln1_g = (const float*)d_in[10]; const float* ln1_b = (const float*)d_in[11];
    const float* gate_w = (const float*)d_in[12]; const float* gate_b = (const float*)d_in[13];
    const float* w1 = (const float*)d_in[14]; const float* b1 = (const float*)d_in[15];
    const float* w2 = (const float*)d_in[16]; const float* b2 = (const float*)d_in[17];
    const float* ln2_g = (const float*)d_in[18]; const float* ln2_b = (const float*)d_in[19];

    float* f32 = nullptr;  __half* f16 = nullptr;
    cudaGetSymbolAddress((void**)&f32, g_f32);
    cudaGetSymbolAddress((void**)&f16, g_f16);

    float*  attn   = f32 + F_ATTN;
    float*  inter  = f32 + F_INT;
    float*  moe    = f32 + F_MOE;
    float*  gate   = f32 + F_GATE;
    float*  qkvb   = f32 + F_QKVB;
    __half* hid16  = f16 + H_HID;
    __half* q16    = f16 + H_Q;
    __half* vT16   = f16 + H_VT;
    __half* ctx16  = f16 + H_CTX;
    __half* int16_ = f16 + H_INT;
    __half* sc16   = f16 + H_SC;
    __half* h16    = f16 + H_HB;
    __half* p2     = f16 + H_P2;
    __half* wqT = f16 + H_WQ;
    __half* woT = f16 + H_WO;
    __half* w1T = f16 + H_W1; __half* w2T = f16 + H_W2;

    float* out = (float*)d_out;
    float* gate_out = nullptr;
    if ((size_t)out_size >= (size_t)NTOK * Dc + (size_t)NTOK * Ec)
        gate_out = out + (size_t)NTOK * Dc;

    cudaFuncSetAttribute(hgemm<128,0>, cudaFuncAttributeMaxDynamicSharedMemorySize, SMEM_NT128);
    cudaFuncSetAttribute(hgemm<128,1>, cudaFuncAttributeMaxDynamicSharedMemorySize, SMEM_NT128);
    cudaFuncSetAttribute(hgemm<128,3>, cudaFuncAttributeMaxDynamicSharedMemorySize, SMEM_NT128);
    cudaFuncSetAttribute(hgemm<128,6>, cudaFuncAttributeMaxDynamicSharedMemorySize, SMEM_NT128);
    cudaFuncSetAttribute(hgemm<128,9>, cudaFuncAttributeMaxDynamicSharedMemorySize, SMEM_NT128);
    cudaFuncSetAttribute(hgemm<64,6>,  cudaFuncAttributeMaxDynamicSharedMemorySize, SMEM_NT64);

    const dim3 blk(256);
    const dim3 tblk(32, 8);

    // 0) hidden conversion + bias pack
    convpack<<<NTOK * Dc / 4 / 256, 256>>>(hidden, hid16, bq, bk, bv, qkvb);
    // 1) ALL weight transposes
    tconv_all<<<69632, tblk>>>(wq, wk, wv, wo, w1, w2, wqT);

    // 2) fused Q/K/V projection (z = 0,1,2 -> q16, k16, vT scatter)
    {
        dim3 grid(Dc / 128, NTOK / 128, 3);
        hgemm<128,9><<<grid, blk, SMEM_NT128>>>(hid16, wqT, nullptr, q16, qkvb, nullptr,
            Dc, Dc, Dc, Dc, 0, 0.f, 3,
            0, 0,
            0, (long long)Dc * Dc,
            0, (long long)NTOK * Dc,
            0, (long long)Dc);
    }

    // 3) scores (fp16) = QK^T/8 + mask, per (b,h)
    {
        dim3 grid(Sc / 128, Sc / 128, Bc * Hc);
        hgemm<128,3><<<grid, blk, SMEM_NT128>>>(q16, q16 + (size_t)NTOK * Dc, nullptr, sc16,
            nullptr, mask,
            DHc, Dc, Dc, Sc, Sc, 0.125f, Hc,
            (long long)Sc * Dc, DHc,
            (long long)Sc * Dc, DHc,
            (long long)Hc * Sc * Sc, (long long)Sc * Sc,
            (long long)Sc * Sc, 0);
    }

    // 4) in-place fp16 softmax
    softmax2048h<<<Bc * Hc * Sc, 256>>>(sc16);

    // 5) ctx = probs @ V   (B operand = vT [DH,S], N=64 per head)
    {
        dim3 grid(1, Sc / 128, Bc * Hc);
        hgemm<64,6><<<grid, blk, SMEM_NT64>>>(sc16, vT16, nullptr, ctx16, nullptr, nullptr,
            Sc, Sc, Sc, Dc, 0, 0.f, Hc,
            (long long)Hc * Sc * Sc, (long long)Sc * Sc,
            (long long)Hc * DHc * Sc, (long long)DHc * Sc,
            (long long)Sc * Dc, (long long)DHc, 0, 0);
    }

    // 6) output projection -> fp32 attn
    {
        dim3 grid(Dc / 128, NTOK / 128, 1);
        hgemm<128,0><<<grid, blk, SMEM_NT128>>>(ctx16, woT, attn, nullptr, bo, nullptr,
            Dc, Dc, Dc, Dc, 0, 0.f, 1, 0,0,0,0,0,0,0,0);
    }

    // 7) inter = LN1(attn + hidden)
    ln_residual<<<NTOK, 256>>>(attn, hidden, ln1_g, ln1_b, inter, int16_);

    // 8) gate
    gate_kernel<<<NTOK, 256>>>(inter, gate_w, gate_b, gate, gate_out);

    // 9-10) MoE batched across experts (z = expert)
    {
        dim3 gh(Fc / 128, NTOK / 128, Ec);
        hgemm<128,1><<<gh, blk, SMEM_NT128>>>(int16_, w1T, nullptr, h16, b1, nullptr,
            Dc, Dc, Dc, Fc, 0, 0.f, Ec,
            0, 0,
            0, (long long)Dc * Fc,
            0, (long long)NTOK * Fc,
            0, (long long)Fc);

        dim3 gy(Dc / 128, NTOK / 128, Ec);
        hgemm<128,6><<<gy, blk, SMEM_NT128>>>(h16, w2T, nullptr, p2, b2, nullptr,
            Fc, Fc, Fc, Dc, 0, 0.f, Ec,
            0, (long long)NTOK * Fc,
            0, (long long)Fc * Dc,
            0, (long long)NTOK * Dc,
            0, (long long)Dc);
    }

    // 11) gate-weighted reduce
    moe_reduce<<<NTOK * Dc / 2 / 256, 256>>>(p2, gate, moe);

    // 12) output = LN2(moe + inter)
    ln_residual<<<NTOK, 256>>>(moe, inter, ln2_g, ln2_b, out, nullptr);
}

// round 8
// speedup vs baseline: 1.6019x; 1.1270x over previous
#include <cuda_runtime.h>
#include <cuda_fp16.h>
#include <math.h>
#include <stdint.h>

// ---------------- problem constants ----------------
#define Bc 2
#define Sc 2048
#define Dc 1024
#define Hc 16
#define DHc 64
#define Fc 4096
#define Ec 8
#define NTOK (Bc * Sc)
#define LN_EPS 1e-6f

// ---------------- fp32 scratch ----------------
static const size_t F_ATTN  = 0;
static const size_t F_INT   = F_ATTN + (size_t)NTOK * Dc;
static const size_t F_MOE   = F_INT  + (size_t)NTOK * Dc;
static const size_t F_GATE  = F_MOE  + (size_t)NTOK * Dc;
static const size_t F_QKVB  = F_GATE + (size_t)NTOK * Ec;
static const size_t F_TOTAL = F_QKVB + 3 * (size_t)Dc;
__device__ float g_f32[F_TOTAL];

// ---------------- fp16 scratch ----------------
static const size_t H_HID  = 0;
static const size_t H_Q    = H_HID + (size_t)NTOK * Dc;
static const size_t H_K    = H_Q   + (size_t)NTOK * Dc;     // contiguous with Q
static const size_t H_VT   = H_K   + (size_t)NTOK * Dc;     // [B,H,DH,S]
static const size_t H_CTX  = H_VT  + (size_t)NTOK * Dc;
static const size_t H_INT  = H_CTX + (size_t)NTOK * Dc;
static const size_t H_MSK  = H_INT + (size_t)NTOK * Dc;                 // fp16 mask [B,S,S]
static const size_t H_HB   = H_MSK + (size_t)Bc * Sc * Sc;
static const size_t H_P2   = H_HB  + (size_t)Ec * NTOK * Fc;
static const size_t H_WQ   = H_P2  + (size_t)Ec * NTOK * Dc;
static const size_t H_W1   = H_WQ  + 4 * (size_t)Dc * Dc;   // [E][N=F,K=D]
static const size_t H_W2   = H_W1  + (size_t)Ec * Dc * Fc;  // [E][N=D,K=F]
static const size_t H_TOTAL= H_W2  + (size_t)Ec * Fc * Dc;
__device__ __half g_f16[H_TOTAL];

// ---------------- PTX helpers ----------------
__device__ __forceinline__ uint32_t smem_u32(const void* p) {
    uint32_t a;
    asm("{ .reg .u64 t; cvta.to.shared.u64 t, %1; cvt.u32.u64 %0, t; }" : "=r"(a) : "l"(p));
    return a;
}
__device__ __forceinline__ void cp16(uint32_t s, const void* g) {
    asm volatile("cp.async.cg.shared.global [%0], [%1], 16;" :: "r"(s), "l"(g));
}
#define CP_COMMIT() asm volatile("cp.async.commit_group;" ::: "memory")
#define CP_WAIT(n)  asm volatile("cp.async.wait_group %0;" :: "n"(n) : "memory")

__device__ __forceinline__ void ldm_x4(uint32_t* r, uint32_t addr) {
    asm volatile("ldmatrix.sync.aligned.m8n8.x4.shared.b16 {%0,%1,%2,%3}, [%4];"
        : "=r"(r[0]), "=r"(r[1]), "=r"(r[2]), "=r"(r[3]) : "r"(addr));
}
__device__ __forceinline__ void mma16816(float* c, const uint32_t* a, const uint32_t* b) {
    asm volatile(
        "mma.sync.aligned.m16n8k16.row.col.f32.f16.f16.f32 "
        "{%0,%1,%2,%3}, {%4,%5,%6,%7}, {%8,%9}, {%0,%1,%2,%3};"
        : "+f"(c[0]), "+f"(c[1]), "+f"(c[2]), "+f"(c[3])
        : "r"(a[0]), "r"(a[1]), "r"(a[2]), "r"(a[3]), "r"(b[0]), "r"(b[1]));
}

__device__ __forceinline__ float gelu_tanh(float x) {
    float x3 = x * x * x;
    float t  = tanhf(0.7978845608028654f * (x + 0.044715f * x3));
    return 0.5f * x * (1.0f + t);
}
__device__ __forceinline__ uint32_t pack_h2(float a, float b) {
    __half2 h = __floats2half2_rn(a, b);
    return *reinterpret_cast<uint32_t*>(&h);
}

// ============================================================================
// HMMA GEMM (unchanged R7 core): C[128,NT] = A[M,K] * B[N,K]^T, BK=64, 3 stages
// EPI: 0 = fp32 C = acc + bias?
//      1 = fp16 C16 = gelu(acc + bias)
//      6 = fp16 C16 = acc + bias?
//      9 = QKV route: hh<2 plain fp16; hh==2 V^T scatter
// ============================================================================
#define SPAD 72
#define STAGES 3

template <int NT, int EPI>
__global__ __launch_bounds__(256)
void hgemm(const __half* __restrict__ A, const __half* __restrict__ B,
           float* __restrict__ C, __half* __restrict__ C16,
           const float* __restrict__ bias,
           int K, int lda, int ldb, int ldc, int Hdim,
           long long aOB, long long aOH, long long bOB, long long bOH,
           long long cOB, long long cOH, long long biasOH)
{
    extern __shared__ __half smem[];

    const int tid = threadIdx.x, wid = tid >> 5, lane = tid & 31;
    const int wm = wid & 3, wn = wid >> 2;
    constexpr int WN = NT / 2;
    constexpr int NF = WN / 8;

    const int m0 = blockIdx.y * 128, n0 = blockIdx.x * NT;
    const int z = blockIdx.z, bb = z / Hdim, hh = z - bb * Hdim;
    A += (size_t)bb * aOB + (size_t)hh * aOH;
    B += (size_t)bb * bOB + (size_t)hh * bOH;
    if (bias) bias += (size_t)hh * biasOH;
    const long long coff = (long long)bb * cOB + (long long)hh * cOH;

    const uint32_t ABUF = 128 * SPAD * 2;
    const uint32_t BBUF = (uint32_t)NT * SPAD * 2;
    const uint32_t abase = smem_u32(smem);
    const uint32_t bbase = abase + STAGES * ABUF;

    const uint32_t a_off = (uint32_t)((wm * 32 + (lane & 15)) * (SPAD * 2) + ((lane >> 4) * 8) * 2);
    const uint32_t b_off = (uint32_t)((wn * WN + (lane & 7) + ((lane >> 4) << 3)) * (SPAD * 2)
                                      + (((lane >> 3) & 1) * 8) * 2);

    float acc[2][NF][4];
#pragma unroll
    for (int i = 0; i < 2; i++)
#pragma unroll
        for (int j = 0; j < NF; j++)
#pragma unroll
            for (int r = 0; r < 4; r++) acc[i][j][r] = 0.0f;

    const int nc = K >> 6;

    auto load_tile = [&](int c, int buf) {
        const __half* Ab = A + (size_t)m0 * lda + (size_t)c * 64;
#pragma unroll
        for (int it = 0; it < 4; it++) {
            int lin = it * 256 + tid;
            int row = lin >> 3, seg = lin & 7;
            cp16(abase + buf * ABUF + row * (SPAD * 2) + seg * 16,
                 Ab + (size_t)row * lda + seg * 8);
        }
        const __half* Bb = B + (size_t)n0 * ldb + (size_t)c * 64;
#pragma unroll
        for (int it = 0; it < NT / 32; it++) {
            int lin = it * 256 + tid;
            int row = lin >> 3, seg = lin & 7;
            cp16(bbase + buf * BBUF + row * (SPAD * 2) + seg * 16,
                 Bb + (size_t)row * ldb + seg * 8);
        }
    };

#pragma unroll
    for (int s = 0; s < STAGES - 1; s++) {
        if (s < nc) load_tile(s, s);
        CP_COMMIT();
    }

    for (int c = 0; c < nc; c++) {
        CP_WAIT(STAGES - 2);
        __syncthreads();
        const int nxt = c + STAGES - 1;
        if (nxt < nc) load_tile(nxt, nxt % STAGES);
        CP_COMMIT();

        const int buf = c % STAGES;
        const uint32_t ab = abase + buf * ABUF + a_off;
        const uint32_t bbf = bbase + buf * BBUF + b_off;

#pragma unroll
        for (int ks = 0; ks < 4; ks++) {
            uint32_t af[2][4];
#pragma unroll
            for (int mi = 0; mi < 2; mi++)
                ldm_x4(af[mi], ab + mi * 16 * (SPAD * 2) + ks * 32);
            uint32_t bf[NF][2];
#pragma unroll
            for (int p = 0; p < NF / 2; p++) {
                uint32_t t[4];
                ldm_x4(t, bbf + p * 16 * (SPAD * 2) + ks * 32);
                bf[2 * p][0] = t[0]; bf[2 * p][1] = t[1];
                bf[2 * p + 1][0] = t[2]; bf[2 * p + 1][1] = t[3];
            }
#pragma unroll
            for (int mi = 0; mi < 2; mi++)
#pragma unroll
                for (int nj = 0; nj < NF; nj++)
                    mma16816(acc[mi][nj], af[mi], bf[nj]);
        }
    }

#pragma unroll
    for (int mi = 0; mi < 2; mi++) {
#pragma unroll
        for (int nj = 0; nj < NF; nj++) {
            const int r0 = m0 + wm * 32 + mi * 16 + (lane >> 2);
            const int cc = n0 + wn * WN + nj * 8 + (lane & 3) * 2;
#pragma unroll
            for (int h = 0; h < 2; h++) {
                const int row = r0 + h * 8;
                const float v0 = acc[mi][nj][2 * h + 0];
                const float v1 = acc[mi][nj][2 * h + 1];
                if (EPI == 0) {
                    float b0 = bias ? bias[cc] : 0.f, b1 = bias ? bias[cc + 1] : 0.f;
                    float2 o = make_float2(v0 + b0, v1 + b1);
                    *(float2*)(C + coff + (size_t)row * ldc + cc) = o;
                } else if (EPI == 1 || EPI == 6) {
                    float o0 = v0 + (bias ? bias[cc] : 0.f);
                    float o1 = v1 + (bias ? bias[cc + 1] : 0.f);
                    if (EPI == 1) { o0 = gelu_tanh(o0); o1 = gelu_tanh(o1); }
                    *(uint32_t*)(C16 + coff + (size_t)row * ldc + cc) = pack_h2(o0, o1);
                } else if (EPI == 9) {
                    float o0 = v0 + bias[cc];
                    float o1 = v1 + bias[cc + 1];
                    if (hh < 2) {
                        *(uint32_t*)(C16 + coff + (size_t)row * ldc + cc) = pack_h2(o0, o1);
                    } else {
                        const int b_ = row >> 11, s_ = row & 2047;
                        const int h0 = cc >> 6, d0 = cc & 63;
                        const int h1 = (cc + 1) >> 6, d1 = (cc + 1) & 63;
                        C16[coff + ((size_t)((b_ * Hc + h0) * DHc + d0)) * Sc + s_] = __float2half(o0);
                        C16[coff + ((size_t)((b_ * Hc + h1) * DHc + d1)) * Sc + s_] = __float2half(o1);
                    }
                }
            }
        }
    }
}

static const int SMEM_NT128 = STAGES * (128 + 128) * SPAD * 2;  // 110592

// ============================================================================
// FlashAttention-2 style fused attention.
// Grid: (S/64 q-tiles, B*H). 128 threads = 4 warps; warp = 16 q rows.
// KV tiles of 128, double-buffered cp.async. Mask fp16 [B,S,S].
// ctx output fp16 [B*S, D] (head h at cols h*64..).
// ============================================================================
#define SP1 72     // K/Q smem row stride (halves)
#define SP2 136    // V^T smem row stride (halves)
static const int SMEM_FA = 64 * SP1 * 2 + 2 * 128 * SP1 * 2 + 2 * 64 * SP2 * 2; // 80896

__global__ __launch_bounds__(128)
void flash_attn(const __half* __restrict__ Qg, const __half* __restrict__ Kg,
                const __half* __restrict__ Vt, const __half* __restrict__ Mk,
                __half* __restrict__ Og)
{
    extern __shared__ __half sm[];
    const int tid = threadIdx.x, wid = tid >> 5, lane = tid & 31;
    const int q0 = blockIdx.x * 64;
    const int z = blockIdx.y, bb = z >> 4, hh = z & 15;

    const uint32_t qs  = smem_u32(sm);
    const uint32_t ks0 = qs + 64 * SP1 * 2;
    const uint32_t KBUF = 128 * SP1 * 2;
    const uint32_t vs0 = ks0 + 2 * KBUF;
    const uint32_t VBUF = 64 * SP2 * 2;

    const __half* Qb = Qg + ((size_t)bb * Sc + q0) * Dc + hh * DHc;
    const __half* Kb = Kg + (size_t)bb * Sc * Dc + hh * DHc;
    const __half* Vb = Vt + ((size_t)(bb * Hc + hh)) * DHc * Sc;
    const __half* Mb = Mk + (size_t)bb * Sc * Sc;

    auto loadKV = [&](int t, int buf) {
        const __half* ksrc = Kb + (size_t)(t * 128) * Dc;
#pragma unroll
        for (int it = 0; it < 8; it++) {
            int lin = it * 128 + tid, row = lin >> 3, seg = lin & 7;
            cp16(ks0 + buf * KBUF + row * (SP1 * 2) + seg * 16, ksrc + (size_t)row * Dc + seg * 8);
        }
#pragma unroll
        for (int it = 0; it < 8; it++) {
            int lin = it * 128 + tid, row = lin >> 4, seg = lin & 15;
            cp16(vs0 + buf * VBUF + row * (SP2 * 2) + seg * 16,
                 Vb + (size_t)row * Sc + t * 128 + seg * 8);
        }
    };

    // prologue: Q + KV(0)
#pragma unroll
    for (int it = 0; it < 4; it++) {
        int lin = it * 128 + tid, row = lin >> 3, seg = lin & 7;
        cp16(qs + row * (SP1 * 2) + seg * 16, Qb + (size_t)row * Dc + seg * 8);
    }
    loadKV(0, 0);
    CP_COMMIT();

    const uint32_t a_q = qs + (wid * 16 + (lane & 15)) * (SP1 * 2) + ((lane >> 4) * 8) * 2;
    const uint32_t b_k = (uint32_t)(((lane & 7) + ((lane >> 4) << 3)) * (SP1 * 2) + (((lane >> 3) & 1) * 8) * 2);
    const uint32_t b_v = (uint32_t)(((lane & 7) + ((lane >> 4) << 3)) * (SP2 * 2) + (((lane >> 3) & 1) * 8) * 2);

    const int r = lane >> 2;
    const int qrow = q0 + wid * 16 + r;        // this thread's row (and +8)

    float o[8][4];
#pragma unroll
    for (int j = 0; j < 8; j++) { o[j][0] = o[j][1] = o[j][2] = o[j][3] = 0.f; }
    float rm0 = -1e30f, rm1 = -1e30f, rl0 = 0.f, rl1 = 0.f;

    for (int t = 0; t < Sc / 128; t++) {
        __syncthreads();                       // all warps done with compute t-1
        if (t + 1 < Sc / 128) loadKV(t + 1, (t + 1) & 1);
        CP_COMMIT();
        CP_WAIT(1);
        __syncthreads();

        const uint32_t kb = ks0 + (t & 1) * KBUF + b_k;
        const uint32_t vb = vs0 + (t & 1) * VBUF + b_v;

        // ---- S = Q K^T  (16 q rows x 128 k cols per warp)
        float s[16][4];
#pragma unroll
        for (int j = 0; j < 16; j++) { s[j][0] = s[j][1] = s[j][2] = s[j][3] = 0.f; }
#pragma unroll
        for (int ks = 0; ks < 4; ks++) {
            uint32_t af[4];
            ldm_x4(af, a_q + ks * 32);
#pragma unroll
            for (int p = 0; p < 8; p++) {
                uint32_t tt[4];
                ldm_x4(tt, kb + p * 16 * (SP1 * 2) + ks * 32);
                mma16816(s[2 * p], af, tt);
                mma16816(s[2 * p + 1], af, tt + 2);
            }
        }

        // ---- scale + mask + row max
        const __half* mr0 = Mb + (size_t)qrow * Sc + t * 128 + (lane & 3) * 2;
        const __half* mr1 = mr0 + 8 * Sc;
        float tm0 = -1e30f, tm1 = -1e30f;
#pragma unroll
        for (int j = 0; j < 16; j++) {
            float2 m0 = __half22float2(*(const __half2*)(mr0 + j * 8));
            float2 m1 = __half22float2(*(const __half2*)(mr1 + j * 8));
            s[j][0] = s[j][0] * 0.125f + m0.x;
            s[j][1] = s[j][1] * 0.125f + m0.y;
            s[j][2] = s[j][2] * 0.125f + m1.x;
            s[j][3] = s[j][3] * 0.125f + m1.y;
            tm0 = fmaxf(tm0, fmaxf(s[j][0], s[j][1]));
            tm1 = fmaxf(tm1, fmaxf(s[j][2], s[j][3]));
        }
#pragma unroll
        for (int off = 1; off <= 2; off <<= 1) {
            tm0 = fmaxf(tm0, __shfl_xor_sync(0xffffffffu, tm0, off));
            tm1 = fmaxf(tm1, __shfl_xor_sync(0xffffffffu, tm1, off));
        }
        const float mn0 = fmaxf(rm0, tm0), mn1 = fmaxf(rm1, tm1);
        const float cr0 = __expf(rm0 - mn0), cr1 = __expf(rm1 - mn1);
        rm0 = mn0; rm1 = mn1;

        // ---- exp + pack P
        uint32_t pk[16][2];
        float ps0 = 0.f, ps1 = 0.f;
#pragma unroll
        for (int j = 0; j < 16; j++) {
            float p0 = __expf(s[j][0] - mn0), p1 = __expf(s[j][1] - mn0);
            float p2 = __expf(s[j][2] - mn1), p3 = __expf(s[j][3] - mn1);
            ps0 += p0 + p1; ps1 += p2 + p3;
            pk[j][0] = pack_h2(p0, p1);
            pk[j][1] = pack_h2(p2, p3);
        }
#pragma unroll
        for (int off = 1; off <= 2; off <<= 1) {
            ps0 += __shfl_xor_sync(0xffffffffu, ps0, off);
            ps1 += __shfl_xor_sync(0xffffffffu, ps1, off);
        }
        rl0 = rl0 * cr0 + ps0;
        rl1 = rl1 * cr1 + ps1;

        // ---- rescale O
#pragma unroll
        for (int j = 0; j < 8; j++) {
            o[j][0] *= cr0; o[j][1] *= cr0;
            o[j][2] *= cr1; o[j][3] *= cr1;
        }

        // ---- O += P @ V  (k = 128 s-keys, 8 k-steps)
#pragma unroll
        for (int ks = 0; ks < 8; ks++) {
            uint32_t af[4] = { pk[2 * ks][0], pk[2 * ks][1], pk[2 * ks + 1][0], pk[2 * ks + 1][1] };
#pragma unroll
            for (int p = 0; p < 4; p++) {
                uint32_t tt[4];
                ldm_x4(tt, vb + p * 16 * (SP2 * 2) + ks * 32);
                mma16816(o[2 * p], af, tt);
                mma16816(o[2 * p + 1], af, tt + 2);
            }
        }
    }

    // ---- write O / l
    const float i0 = 1.0f / rl0, i1 = 1.0f / rl1;
    __half* or0 = Og + ((size_t)bb * Sc + qrow) * Dc + hh * DHc + (lane & 3) * 2;
    __half* or1 = or0 + 8 * Dc;
#pragma unroll
    for (int j = 0; j < 8; j++) {
        *(uint32_t*)(or0 + j * 8) = pack_h2(o[j][0] * i0, o[j][1] * i0);
        *(uint32_t*)(or1 + j * 8) = pack_h2(o[j][2] * i1, o[j][3] * i1);
    }
}

// ---------------- small kernels ----------------
__global__ void convpack(const float* __restrict__ s, __half* __restrict__ d,
                         const float* __restrict__ bq, const float* __restrict__ bk,
                         const float* __restrict__ bv, float* __restrict__ qkvb)
{
    int i = blockIdx.x * blockDim.x + threadIdx.x;
    if (i < NTOK * Dc / 4) {
        float4 v = ((const float4*)s)[i];
        uint2 u;
        u.x = pack_h2(v.x, v.y); u.y = pack_h2(v.z, v.w);
        ((uint2*)d)[i] = u;
    }
    if (i < Dc) { qkvb[i] = bq[i]; qkvb[Dc + i] = bk[i]; qkvb[2 * Dc + i] = bv[i]; }
}

__global__ void maskconv(const float* __restrict__ s, __half* __restrict__ d)
{
    int i = blockIdx.x * blockDim.x + threadIdx.x;   // over B*S*S/4
    float4 v = ((const float4*)s)[i];
    uint2 u;
    u.x = pack_h2(v.x, v.y); u.y = pack_h2(v.z, v.w);
    ((uint2*)d)[i] = u;
}

__global__ void tconv_all(const float* __restrict__ wq, const float* __restrict__ wk,
                          const float* __restrict__ wv, const float* __restrict__ wo,
                          const float* __restrict__ w1, const float* __restrict__ w2,
                          __half* __restrict__ dstbase)
{
    __shared__ float t[32][33];
    int b = blockIdx.x;
    const float* src; __half* dst; int K, N;
    if (b < 4096) {
        int m = b >> 10; b &= 1023;
        src = (m == 0) ? wq : (m == 1) ? wk : (m == 2) ? wv : wo;
        dst = dstbase + (size_t)m * Dc * Dc; K = Dc; N = Dc;
    } else if (b < 4096 + 32768) {
        b -= 4096; int e = b >> 12; b &= 4095;
        src = w1 + (size_t)e * Dc * Fc;
        dst = dstbase + 4 * (size_t)Dc * Dc + (size_t)e * Dc * Fc; K = Dc; N = Fc;
    } else {
        b -= 36864; int e = b >> 12; b &= 4095;
        src = w2 + (size_t)e * Fc * Dc;
        dst = dstbase + 4 * (size_t)Dc * Dc + (size_t)Ec * Dc * Fc + (size_t)e * Fc * Dc;
        K = Fc; N = Dc;
    }
    const int ntx = N / 32;
    const int k0 = (b / ntx) * 32, n0 = (b % ntx) * 32;
    const int x = threadIdx.x, y = threadIdx.y;
#pragma unroll
    for (int i = 0; i < 32; i += 8)
        t[y + i][x] = src[(size_t)(k0 + y + i) * N + n0 + x];
    __syncthreads();
#pragma unroll
    for (int i = 0; i < 32; i += 8)
        dst[(size_t)(n0 + y + i) * K + k0 + x] = __float2half(t[x][y + i]);
}

__global__ void ln_residual(const float* __restrict__ x, const float* __restrict__ r,
                            const float* __restrict__ g, const float* __restrict__ b,
                            float* __restrict__ out, __half* __restrict__ out16)
{
    __shared__ float red[256];
    const size_t base = (size_t)blockIdx.x * Dc;
    const int tid = threadIdx.x;
    float v[4]; float s = 0.f;
#pragma unroll
    for (int i = 0; i < 4; i++) { const int c = tid + i * 256; v[i] = x[base + c] + r[base + c]; s += v[i]; }
    red[tid] = s; __syncthreads();
    for (int st = 128; st > 0; st >>= 1) { if (tid < st) red[tid] += red[tid + st]; __syncthreads(); }
    const float mean = red[0] * (1.0f / Dc); __syncthreads();
    float ss = 0.f;
#pragma unroll
    for (int i = 0; i < 4; i++) { const float d = v[i] - mean; ss += d * d; }
    red[tid] = ss; __syncthreads();
    for (int st = 128; st > 0; st >>= 1) { if (tid < st) red[tid] += red[tid + st]; __syncthreads(); }
    const float rstd = rsqrtf(red[0] * (1.0f / Dc) + LN_EPS);
#pragma unroll
    for (int i = 0; i < 4; i++) {
        const int c = tid + i * 256;
        const float o = (v[i] - mean) * rstd * g[c] + b[c];
        out[base + c] = o;
        if (out16) out16[base + c] = __float2half(o);
    }
}

__global__ void gate_kernel(const float* __restrict__ x, const float* __restrict__ gw,
                            const float* __restrict__ gb,
                            float* __restrict__ gate, float* __restrict__ gate_out)
{
    const int m = blockIdx.x;
    const int tid = threadIdx.x;
    const int wid = tid >> 5, lane = tid & 31;
    __shared__ float logits[Ec];
    float s = 0.f;
    const float* xr = x + (size_t)m * Dc;
    for (int d = lane; d < Dc; d += 32) s += xr[d] * gw[d * Ec + wid];
#pragma unroll
    for (int o = 16; o > 0; o >>= 1) s += __shfl_down_sync(0xffffffffu, s, o);
    if (lane == 0) logits[wid] = s + gb[wid];
    __syncthreads();
    if (tid == 0) {
        float mx = logits[0];
#pragma unroll
        for (int e = 1; e < Ec; e++) mx = fmaxf(mx, logits[e]);
        float p[Ec]; float sum = 0.f;
#pragma unroll
        for (int e = 0; e < Ec; e++) { p[e] = expf(logits[e] - mx); sum += p[e]; }
        const float inv = 1.0f / sum;
#pragma unroll
        for (int e = 0; e < Ec; e++) {
            const float pv = p[e] * inv;
            gate[(size_t)m * Ec + e] = pv;
            if (gate_out) gate_out[(size_t)m * Ec + e] = pv;
        }
    }
}

__global__ void moe_reduce(const __half* __restrict__ part, const float* __restrict__ gate,
                           float* __restrict__ outm)
{
    const int i = blockIdx.x * blockDim.x + threadIdx.x;
    const int m = i / (Dc / 2);
    const float* gm = gate + (size_t)m * Ec;
    float2 s = make_float2(0.f, 0.f);
#pragma unroll
    for (int e = 0; e < Ec; e++) {
        float2 f = __half22float2(((const __half2*)part)[(size_t)e * (NTOK * Dc / 2) + i]);
        const float g = gm[e];
        s.x += g * f.x; s.y += g * f.y;
    }
    ((float2*)outm)[i] = s;
}

// ---------------- launch ----------------------------------------------------
extern "C" void kernel_launch(void* const* d_in, const int* in_sizes, int n_in,
                              void* d_out, int out_size)
{
    const float* hidden = (const float*)d_in[0];
    const float* mask   = (const float*)d_in[1];
    const float* wq = (const float*)d_in[2];  const float* bq = (const float*)d_in[3];
    const float* wk = (const float*)d_in[4];  const float* bk = (const float*)d_in[5];
    const float* wv = (const float*)d_in[6];  const float* bv = (const float*)d_in[7];
    const float* wo = (const float*)d_in[8];  const float* bo = (const float*)d_in[9];
    const float* ln1_g = (const float*)d_in[10]; const float* ln1_b = (const float*)d_in[11];
    const float* gate_w = (const float*)d_in[12]; const float* gate_b = (const float*)d_in[13];
    const float* w1 = (const float*)d_in[14]; const float* b1 = (const float*)d_in[15];
    const float* w2 = (const float*)d_in[16]; const float* b2 = (const float*)d_in[17];
    const float* ln2_g = (const float*)d_in[18]; const float* ln2_b = (const float*)d_in[19];

    float* f32 = nullptr;  __half* f16 = nullptr;
    cudaGetSymbolAddress((void**)&f32, g_f32);
    cudaGetSymbolAddress((void**)&f16, g_f16);

    float*  attn   = f32 + F_ATTN;
    float*  inter  = f32 + F_INT;
    float*  moe    = f32 + F_MOE;
    float*  gate   = f32 + F_GATE;
    float*  qkvb   = f32 + F_QKVB;
    __half* hid16  = f16 + H_HID;
    __half* q16    = f16 + H_Q;
    __half* k16    = f16 + H_K;
    __half* vT16   = f16 + H_VT;
    __half* ctx16  = f16 + H_CTX;
    __half* int16_ = f16 + H_INT;
    __half* msk16  = f16 + H_MSK;
    __half* h16    = f16 + H_HB;
    __half* p2     = f16 + H_P2;
    __half* wqT = f16 + H_WQ;
    __half* woT = f16 + H_WQ + 3 * (size_t)Dc * Dc;
    __half* w1T = f16 + H_W1; __half* w2T = f16 + H_W2;

    float* out = (float*)d_out;
    float* gate_out = nullptr;
    if ((size_t)out_size >= (size_t)NTOK * Dc + (size_t)NTOK * Ec)
        gate_out = out + (size_t)NTOK * Dc;

    cudaFuncSetAttribute(hgemm<128,0>, cudaFuncAttributeMaxDynamicSharedMemorySize, SMEM_NT128);
    cudaFuncSetAttribute(hgemm<128,1>, cudaFuncAttributeMaxDynamicSharedMemorySize, SMEM_NT128);
    cudaFuncSetAttribute(hgemm<128,6>, cudaFuncAttributeMaxDynamicSharedMemorySize, SMEM_NT128);
    cudaFuncSetAttribute(hgemm<128,9>, cudaFuncAttributeMaxDynamicSharedMemorySize, SMEM_NT128);
    cudaFuncSetAttribute(flash_attn,   cudaFuncAttributeMaxDynamicSharedMemorySize, SMEM_FA);

    const dim3 blk(256);
    const dim3 tblk(32, 8);

    // 0) hidden conversion + bias pack
    convpack<<<NTOK * Dc / 4 / 256, 256>>>(hidden, hid16, bq, bk, bv, qkvb);
    // 1) mask -> fp16
    maskconv<<<(int)((size_t)Bc * Sc * Sc / 4 / 256), 256>>>(mask, msk16);
    // 2) all weight transposes
    tconv_all<<<69632, tblk>>>(wq, wk, wv, wo, w1, w2, wqT);

    // 3) fused Q/K/V projection (z = 0,1,2 -> q16, k16, vT scatter)
    {
        dim3 grid(Dc / 128, NTOK / 128, 3);
        hgemm<128,9><<<grid, blk, SMEM_NT128>>>(hid16, wqT, nullptr, q16, qkvb,
            Dc, Dc, Dc, Dc, 3,
            0, 0,
            0, (long long)Dc * Dc,
            0, (long long)NTOK * Dc,
            (long long)Dc);
    }

    // 4) fused attention (scores + softmax + PV) -> ctx16
    {
        dim3 grid(Sc / 64, Bc * Hc);
        flash_attn<<<grid, 128, SMEM_FA>>>(q16, k16, vT16, msk16, ctx16);
    }

    // 5) output projection -> fp32 attn
    {
        dim3 grid(Dc / 128, NTOK / 128, 1);
        hgemm<128,0><<<grid, blk, SMEM_NT128>>>(ctx16, woT, attn, nullptr, bo,
            Dc, Dc, Dc, Dc, 1, 0,0,0,0,0,0,0);
    }

    // 6) inter = LN1(attn + hidden)
    ln_residual<<<NTOK, 256>>>(attn, hidden, ln1_g, ln1_b, inter, int16_);

    // 7) gate
    gate_kernel<<<NTOK, 256>>>(inter, gate_w, gate_b, gate, gate_out);

    // 8-9) MoE batched across experts (z = expert)
    {
        dim3 gh(Fc / 128, NTOK / 128, Ec);
        hgemm<128,1><<<gh, blk, SMEM_NT128>>>(int16_, w1T, nullptr, h16, b1,
            Dc, Dc, Dc, Fc, Ec,
            0, 0,
            0, (long long)Dc * Fc,
            0, (long long)NTOK * Fc,
            (long long)Fc);

        dim3 gy(Dc / 128, NTOK / 128, Ec);
        hgemm<128,6><<<gy, blk, SMEM_NT128>>>(h16, w2T, nullptr, p2, b2,
            Fc, Fc, Fc, Dc, Ec,
            0, (long long)NTOK * Fc,
            0, (long long)Fc * Dc,
            0, (long long)NTOK * Dc,
            (long long)Dc);
    }

    // 10) gate-weighted reduce
    moe_reduce<<<NTOK * Dc / 2 / 256, 256>>>(p2, gate, moe);

    // 11) output = LN2(moe + inter)
    ln_residual<<<NTOK, 256>>>(moe, inter, ln2_g, ln2_b, out, nullptr);
}